// round 1
// baseline (speedup 1.0000x reference)
#include <cuda_runtime.h>
#include <cstddef>

// Problem constants
#define BB 2
#define SS 2048
#define DD 1024
#define HH 16
#define DK 64
#define BSM (BB*SS)          // 4096 rows for the projection GEMMs

// Scratch (device globals; allocation-free per harness rules). 4 x 16MB = 64MB.
__device__ float g_Q[(size_t)BB*HH*SS*DK];
__device__ float g_K[(size_t)BB*HH*SS*DK];
__device__ float g_V[(size_t)BB*HH*SS*DK];
__device__ float g_X[(size_t)BB*SS*DD];

// ---------------------------------------------------------------------------
// GEMM-NT: Dst[m,n] = sum_k A[m,k] * W[n,k] + Bias[n]
// M=4096, N=1024, K=1024. Block tile 64x64, K-tile 16, 256 threads, 4x4 micro.
// SPLIT=true writes in head-split layout [B,H,S,DK]; else plain [M,N].
// ---------------------------------------------------------------------------
template<bool SPLIT>
__global__ __launch_bounds__(256)
void gemm_nt_kernel(const float* __restrict__ A,
                    const float* __restrict__ W,
                    const float* __restrict__ Bias,
                    float* __restrict__ Dst)
{
    const int m0 = blockIdx.y * 64;
    const int n0 = blockIdx.x * 64;

    __shared__ float As[16][64];   // [k][m]
    __shared__ float Bs[16][64];   // [k][n]

    const int tid = threadIdx.x;
    const int tx  = tid & 15;      // n micro-group
    const int ty  = tid >> 4;      // m micro-group

    const int lr = tid >> 2;          // 0..63 : row within tile
    const int lc = (tid & 3) * 4;     // 0,4,8,12 : col within k-tile

    float acc[4][4] = {};

    for (int k0 = 0; k0 < DD; k0 += 16) {
        float4 a4 = *(const float4*)&A[(size_t)(m0 + lr) * DD + k0 + lc];
        float4 w4 = *(const float4*)&W[(size_t)(n0 + lr) * DD + k0 + lc];
        __syncthreads();   // previous compute done before overwriting smem
        As[lc+0][lr] = a4.x; As[lc+1][lr] = a4.y;
        As[lc+2][lr] = a4.z; As[lc+3][lr] = a4.w;
        Bs[lc+0][lr] = w4.x; Bs[lc+1][lr] = w4.y;
        Bs[lc+2][lr] = w4.z; Bs[lc+3][lr] = w4.w;
        __syncthreads();
        #pragma unroll
        for (int kk = 0; kk < 16; ++kk) {
            float4 av = *(const float4*)&As[kk][ty*4];
            float4 bv = *(const float4*)&Bs[kk][tx*4];
            acc[0][0] += av.x*bv.x; acc[0][1] += av.x*bv.y; acc[0][2] += av.x*bv.z; acc[0][3] += av.x*bv.w;
            acc[1][0] += av.y*bv.x; acc[1][1] += av.y*bv.y; acc[1][2] += av.y*bv.z; acc[1][3] += av.y*bv.w;
            acc[2][0] += av.z*bv.x; acc[2][1] += av.z*bv.y; acc[2][2] += av.z*bv.z; acc[2][3] += av.z*bv.w;
            acc[3][0] += av.w*bv.x; acc[3][1] += av.w*bv.y; acc[3][2] += av.w*bv.z; acc[3][3] += av.w*bv.w;
        }
    }

    // epilogue
    const float4 b4 = *(const float4*)&Bias[n0 + tx*4];
    #pragma unroll
    for (int i = 0; i < 4; ++i) {
        const int m = m0 + ty*4 + i;
        float4 o;
        o.x = acc[i][0] + b4.x;
        o.y = acc[i][1] + b4.y;
        o.z = acc[i][2] + b4.z;
        o.w = acc[i][3] + b4.w;
        if (SPLIT) {
            // [B,S,D] row m, col n -> [B,H,S,DK]
            const int b = m >> 11;              // /S
            const int s = m & (SS - 1);
            const int h = n0 >> 6;              // n-tile aligned to DK
            const int dk = tx * 4;              // n within head
            float* dst = Dst + (((size_t)(b*HH + h) * SS + s) * DK + dk);
            *(float4*)dst = o;
        } else {
            *(float4*)&Dst[(size_t)m * DD + n0 + tx*4] = o;
        }
    }
}

// ---------------------------------------------------------------------------
// Attention (linear part: masked scaled QK^T times V, streamed over keys),
// fused with softmax over DK=64 and transpose back to [B,S,D].
// Grid: (S/64, B*H). Block 256 threads. Query tile 64, key chunk 32.
// ---------------------------------------------------------------------------
__global__ __launch_bounds__(256)
void attn_kernel(const int* __restrict__ mask, float* __restrict__ X)
{
    const int qt = blockIdx.x;        // query tile
    const int bh = blockIdx.y;        // b*H + h
    const int b  = bh >> 4;           // /H
    const int h  = bh & (HH - 1);
    const int q0 = qt * 64;

    const float* Qh = g_Q + (size_t)bh * SS * DK;
    const float* Kh = g_K + (size_t)bh * SS * DK;
    const float* Vh = g_V + (size_t)bh * SS * DK;
    const int* maskb = mask + (size_t)b * SS * SS;

    __shared__ float Qs[64][64];   // [d][q]  16KB
    __shared__ float Ks[64][32];   // [d][k]   8KB
    __shared__ float Vs[32][64];   // [k][d]   8KB
    __shared__ float Sc[64][36];   // [q][k] padded  9.2KB

    const int tid = threadIdx.x;

    // Load Q tile transposed: Qs[d][q]
    #pragma unroll
    for (int it = 0; it < 4; ++it) {
        const int linear = tid + it*256;  // 0..1023 float4 slots
        const int d4 = linear >> 6;       // 0..15
        const int q  = linear & 63;
        float4 v = *(const float4*)&Qh[(size_t)(q0 + q) * DK + d4*4];
        Qs[d4*4+0][q] = v.x; Qs[d4*4+1][q] = v.y;
        Qs[d4*4+2][q] = v.z; Qs[d4*4+3][q] = v.w;
    }

    const int tx1 = tid & 7,  ty1 = tid >> 3;   // stage1: 2q x 4k
    const int tx2 = tid & 15, ty2 = tid >> 4;   // stage2: 4q x 4d

    float acc[4][4] = {};

    for (int k0 = 0; k0 < SS; k0 += 32) {
        __syncthreads();  // prior stage2 done with Ks/Vs/Sc; also covers Qs fill (first iter)
        // Load K chunk transposed: Ks[d][k]
        #pragma unroll
        for (int it = 0; it < 2; ++it) {
            const int linear = tid + it*256;   // 0..511
            const int d4 = linear >> 5;        // 0..15
            const int kr = linear & 31;
            float4 v = *(const float4*)&Kh[(size_t)(k0 + kr) * DK + d4*4];
            Ks[d4*4+0][kr] = v.x; Ks[d4*4+1][kr] = v.y;
            Ks[d4*4+2][kr] = v.z; Ks[d4*4+3][kr] = v.w;
        }
        // Load V chunk row-major: Vs[k][d]
        #pragma unroll
        for (int it = 0; it < 2; ++it) {
            const int linear = tid + it*256;
            const int kr = linear >> 4;
            const int d4 = linear & 15;
            *(float4*)&Vs[kr][d4*4] = *(const float4*)&Vh[(size_t)(k0 + kr) * DK + d4*4];
        }
        __syncthreads();

        // Stage 1: Sc[q][k] = (Q . K)/8, masked
        {
            float s0x=0.f,s0y=0.f,s0z=0.f,s0w=0.f;
            float s1x=0.f,s1y=0.f,s1z=0.f,s1w=0.f;
            #pragma unroll
            for (int kk = 0; kk < 64; ++kk) {
                float2 av = *(const float2*)&Qs[kk][ty1*2];
                float4 bv = *(const float4*)&Ks[kk][tx1*4];
                s0x += av.x*bv.x; s0y += av.x*bv.y; s0z += av.x*bv.z; s0w += av.x*bv.w;
                s1x += av.y*bv.x; s1y += av.y*bv.y; s1z += av.y*bv.z; s1w += av.y*bv.w;
            }
            const size_t mrow0 = (size_t)(q0 + ty1*2 + 0) * SS + k0 + tx1*4;
            const size_t mrow1 = (size_t)(q0 + ty1*2 + 1) * SS + k0 + tx1*4;
            float4 o0, o1;
            o0.x = (maskb[mrow0+0]==0) ? -1e9f : s0x*0.125f;
            o0.y = (maskb[mrow0+1]==0) ? -1e9f : s0y*0.125f;
            o0.z = (maskb[mrow0+2]==0) ? -1e9f : s0z*0.125f;
            o0.w = (maskb[mrow0+3]==0) ? -1e9f : s0w*0.125f;
            o1.x = (maskb[mrow1+0]==0) ? -1e9f : s1x*0.125f;
            o1.y = (maskb[mrow1+1]==0) ? -1e9f : s1y*0.125f;
            o1.z = (maskb[mrow1+2]==0) ? -1e9f : s1z*0.125f;
            o1.w = (maskb[mrow1+3]==0) ? -1e9f : s1w*0.125f;
            *(float4*)&Sc[ty1*2+0][tx1*4] = o0;
            *(float4*)&Sc[ty1*2+1][tx1*4] = o1;
        }
        __syncthreads();

        // Stage 2: acc += Sc @ Vs
        #pragma unroll
        for (int kc = 0; kc < 32; ++kc) {
            float a0 = Sc[ty2*4+0][kc];
            float a1 = Sc[ty2*4+1][kc];
            float a2 = Sc[ty2*4+2][kc];
            float a3 = Sc[ty2*4+3][kc];
            float4 bv = *(const float4*)&Vs[kc][tx2*4];
            acc[0][0] += a0*bv.x; acc[0][1] += a0*bv.y; acc[0][2] += a0*bv.z; acc[0][3] += a0*bv.w;
            acc[1][0] += a1*bv.x; acc[1][1] += a1*bv.y; acc[1][2] += a1*bv.z; acc[1][3] += a1*bv.w;
            acc[2][0] += a2*bv.x; acc[2][1] += a2*bv.y; acc[2][2] += a2*bv.z; acc[2][3] += a2*bv.w;
            acc[3][0] += a3*bv.x; acc[3][1] += a3*bv.y; acc[3][2] += a3*bv.z; acc[3][3] += a3*bv.w;
        }
    }

    // Softmax over the 64-wide d dimension: each row is held by 16 lanes (tx2),
    // each lane has 4 of 64 values. Reduce with width-16 shuffles.
    #pragma unroll
    for (int i = 0; i < 4; ++i) {
        float m = fmaxf(fmaxf(acc[i][0], acc[i][1]), fmaxf(acc[i][2], acc[i][3]));
        #pragma unroll
        for (int off = 8; off >= 1; off >>= 1)
            m = fmaxf(m, __shfl_xor_sync(0xffffffffu, m, off, 16));
        float e0 = __expf(acc[i][0] - m);
        float e1 = __expf(acc[i][1] - m);
        float e2 = __expf(acc[i][2] - m);
        float e3 = __expf(acc[i][3] - m);
        float sum = e0 + e1 + e2 + e3;
        #pragma unroll
        for (int off = 8; off >= 1; off >>= 1)
            sum += __shfl_xor_sync(0xffffffffu, sum, off, 16);
        const float inv = 1.0f / sum;
        float4 o = { e0*inv, e1*inv, e2*inv, e3*inv };
        const int s = q0 + ty2*4 + i;
        const int col = h * DK + tx2*4;
        *(float4*)&X[((size_t)b * SS + s) * DD + col] = o;
    }
}

// ---------------------------------------------------------------------------
// Launch
// ---------------------------------------------------------------------------
extern "C" void kernel_launch(void* const* d_in, const int* in_sizes, int n_in,
                              void* d_out, int out_size)
{
    (void)in_sizes; (void)n_in; (void)out_size;
    const float* k_in = (const float*)d_in[0];
    const float* q_in = (const float*)d_in[1];
    const float* v_in = (const float*)d_in[2];
    const int*   mask = (const int*)  d_in[3];
    const float* Wq = (const float*)d_in[4];
    const float* bq = (const float*)d_in[5];
    const float* Wk = (const float*)d_in[6];
    const float* bk = (const float*)d_in[7];
    const float* Wv = (const float*)d_in[8];
    const float* bv = (const float*)d_in[9];
    const float* Wo = (const float*)d_in[10];
    const float* bo = (const float*)d_in[11];
    float* out = (float*)d_out;

    float *pQ, *pK, *pV, *pX;
    cudaGetSymbolAddress((void**)&pQ, g_Q);
    cudaGetSymbolAddress((void**)&pK, g_K);
    cudaGetSymbolAddress((void**)&pV, g_V);
    cudaGetSymbolAddress((void**)&pX, g_X);

    dim3 ggemm(DD/64, BSM/64);   // 16 x 64
    gemm_nt_kernel<true><<<ggemm, 256>>>(q_in, Wq, bq, pQ);
    gemm_nt_kernel<true><<<ggemm, 256>>>(k_in, Wk, bk, pK);
    gemm_nt_kernel<true><<<ggemm, 256>>>(v_in, Wv, bv, pV);

    dim3 gattn(SS/64, BB*HH);    // 32 x 32
    attn_kernel<<<gattn, 256>>>(mask, pX);

    gemm_nt_kernel<false><<<ggemm, 256>>>(pX, Wo, bo, out);
}

// round 2
// speedup vs baseline: 1.1020x; 1.1020x over previous
#include <cuda_runtime.h>
#include <cstddef>

// Problem constants
#define BB 2
#define SS 2048
#define DD 1024
#define HH 16
#define DK 64
#define BSM (BB*SS)          // 4096 rows for the projection GEMMs

typedef unsigned long long u64;

// Scratch (device globals; allocation-free per harness rules). 4 x 16MB = 64MB.
__device__ float g_Q[(size_t)BB*HH*SS*DK];
__device__ float g_K[(size_t)BB*HH*SS*DK];
__device__ float g_V[(size_t)BB*HH*SS*DK];
__device__ float g_X[(size_t)BB*SS*DD];

// ---------------------------------------------------------------------------
// Packed fp32x2 helpers (Blackwell sm_100+: fma.rn.f32x2 on the fma pipe,
// 2x fp32 FLOP per issue slot vs scalar FFMA)
// ---------------------------------------------------------------------------
__device__ __forceinline__ u64 pack2(float lo, float hi) {
    u64 r;
    asm("mov.b64 %0, {%1, %2};" : "=l"(r)
        : "r"(__float_as_uint(lo)), "r"(__float_as_uint(hi)));
    return r;
}
__device__ __forceinline__ u64 bcast2(float x) { return pack2(x, x); }
__device__ __forceinline__ void fma2(u64 &d, u64 a, u64 b) {
    asm("fma.rn.f32x2 %0, %1, %2, %0;" : "+l"(d) : "l"(a), "l"(b));
}
__device__ __forceinline__ float2 unpack2(u64 v) {
    unsigned lo, hi;
    asm("mov.b64 {%0, %1}, %2;" : "=r"(lo), "=r"(hi) : "l"(v));
    return make_float2(__uint_as_float(lo), __uint_as_float(hi));
}

// ---------------------------------------------------------------------------
// GEMM-NT: Dst[m,n] = sum_k A[m,k] * W[n,k] + Bias[n]
// M=4096, N=1024, K=1024. Block tile 128x128, K-tile 16, 256 threads,
// 8x8 micro-tile in f32x2, double-buffered smem.
// SPLIT=true writes head-split layout [B,H,S,DK]; else plain [M,N].
// ---------------------------------------------------------------------------
template<bool SPLIT>
__global__ __launch_bounds__(256, 2)
void gemm_nt_kernel(const float* __restrict__ A,
                    const float* __restrict__ W,
                    const float* __restrict__ Bias,
                    float* __restrict__ Dst)
{
    const int m0 = blockIdx.y * 128;
    const int n0 = blockIdx.x * 128;

    __shared__ float As[2][16][128];   // [buf][k][m]  8KB each
    __shared__ float Bs[2][16][128];   // [buf][k][n]

    const int tid = threadIdx.x;
    const int tx  = tid & 15;          // n micro-group (8 cols)
    const int ty  = tid >> 4;          // m micro-group (8 rows)

    // global-load mapping: 512 float4 per operand tile, 2 per thread
    const int r0 = tid >> 2;           // rows 0..63
    const int r1 = r0 + 64;            // rows 64..127
    const int c4 = (tid & 3) * 4;      // k offset 0,4,8,12

    const float* pA0 = A + (size_t)(m0 + r0) * DD + c4;
    const float* pA1 = A + (size_t)(m0 + r1) * DD + c4;
    const float* pW0 = W + (size_t)(n0 + r0) * DD + c4;
    const float* pW1 = W + (size_t)(n0 + r1) * DD + c4;

    // prologue: tile 0
    float4 ra0 = *(const float4*)(pA0);
    float4 ra1 = *(const float4*)(pA1);
    float4 rb0 = *(const float4*)(pW0);
    float4 rb1 = *(const float4*)(pW1);

    As[0][c4+0][r0] = ra0.x; As[0][c4+1][r0] = ra0.y; As[0][c4+2][r0] = ra0.z; As[0][c4+3][r0] = ra0.w;
    As[0][c4+0][r1] = ra1.x; As[0][c4+1][r1] = ra1.y; As[0][c4+2][r1] = ra1.z; As[0][c4+3][r1] = ra1.w;
    Bs[0][c4+0][r0] = rb0.x; Bs[0][c4+1][r0] = rb0.y; Bs[0][c4+2][r0] = rb0.z; Bs[0][c4+3][r0] = rb0.w;
    Bs[0][c4+0][r1] = rb1.x; Bs[0][c4+1][r1] = rb1.y; Bs[0][c4+2][r1] = rb1.z; Bs[0][c4+3][r1] = rb1.w;
    __syncthreads();

    u64 acc[8][4] = {};   // 8 m-rows x 4 n-pairs

    int cur = 0;
    for (int t = 0; t < 64; ++t) {
        if (t < 63) {
            const int off = (t + 1) * 16;
            ra0 = *(const float4*)(pA0 + off);
            ra1 = *(const float4*)(pA1 + off);
            rb0 = *(const float4*)(pW0 + off);
            rb1 = *(const float4*)(pW1 + off);
        }
        #pragma unroll
        for (int kk = 0; kk < 16; ++kk) {
            float4 a0 = *(const float4*)&As[cur][kk][ty*8];
            float4 a1 = *(const float4*)&As[cur][kk][ty*8 + 4];
            const u64* bp = (const u64*)&Bs[cur][kk][tx*8];
            u64 b0 = bp[0], b1 = bp[1], b2 = bp[2], b3 = bp[3];
            u64 az[8];
            az[0] = bcast2(a0.x); az[1] = bcast2(a0.y);
            az[2] = bcast2(a0.z); az[3] = bcast2(a0.w);
            az[4] = bcast2(a1.x); az[5] = bcast2(a1.y);
            az[6] = bcast2(a1.z); az[7] = bcast2(a1.w);
            #pragma unroll
            for (int i = 0; i < 8; ++i) {
                fma2(acc[i][0], az[i], b0);
                fma2(acc[i][1], az[i], b1);
                fma2(acc[i][2], az[i], b2);
                fma2(acc[i][3], az[i], b3);
            }
        }
        if (t < 63) {
            const int nxt = cur ^ 1;
            As[nxt][c4+0][r0] = ra0.x; As[nxt][c4+1][r0] = ra0.y; As[nxt][c4+2][r0] = ra0.z; As[nxt][c4+3][r0] = ra0.w;
            As[nxt][c4+0][r1] = ra1.x; As[nxt][c4+1][r1] = ra1.y; As[nxt][c4+2][r1] = ra1.z; As[nxt][c4+3][r1] = ra1.w;
            Bs[nxt][c4+0][r0] = rb0.x; Bs[nxt][c4+1][r0] = rb0.y; Bs[nxt][c4+2][r0] = rb0.z; Bs[nxt][c4+3][r0] = rb0.w;
            Bs[nxt][c4+0][r1] = rb1.x; Bs[nxt][c4+1][r1] = rb1.y; Bs[nxt][c4+2][r1] = rb1.z; Bs[nxt][c4+3][r1] = rb1.w;
            __syncthreads();
            cur = nxt;
        }
    }

    // epilogue
    const int nb = n0 + tx * 8;
    const float4 bb0 = *(const float4*)&Bias[nb];
    const float4 bb1 = *(const float4*)&Bias[nb + 4];
    #pragma unroll
    for (int i = 0; i < 8; ++i) {
        const int m = m0 + ty * 8 + i;
        float2 p0 = unpack2(acc[i][0]);
        float2 p1 = unpack2(acc[i][1]);
        float2 p2 = unpack2(acc[i][2]);
        float2 p3 = unpack2(acc[i][3]);
        float4 o0 = { p0.x + bb0.x, p0.y + bb0.y, p1.x + bb0.z, p1.y + bb0.w };
        float4 o1 = { p2.x + bb1.x, p2.y + bb1.y, p3.x + bb1.z, p3.y + bb1.w };
        if (SPLIT) {
            const int b  = m >> 11;
            const int s  = m & (SS - 1);
            const int h  = nb >> 6;
            const int dk = nb & 63;
            float* dst = Dst + (((size_t)(b*HH + h) * SS + s) * DK + dk);
            *(float4*)dst       = o0;
            *(float4*)(dst + 4) = o1;
        } else {
            float* dst = Dst + (size_t)m * DD + nb;
            *(float4*)dst       = o0;
            *(float4*)(dst + 4) = o1;
        }
    }
}

// ---------------------------------------------------------------------------
// Attention (linear part: masked scaled QK^T times V, streamed over keys),
// fused with softmax over DK=64 and transpose back to [B,S,D].
// Grid: (S/64, B*H). Block 256 threads. Query tile 64, key chunk 32.
// Inner products in f32x2.
// ---------------------------------------------------------------------------
__global__ __launch_bounds__(256)
void attn_kernel(const int* __restrict__ mask, float* __restrict__ X)
{
    const int qt = blockIdx.x;        // query tile
    const int bh = blockIdx.y;        // b*H + h
    const int b  = bh >> 4;           // /H
    const int h  = bh & (HH - 1);
    const int q0 = qt * 64;

    const float* Qh = g_Q + (size_t)bh * SS * DK;
    const float* Kh = g_K + (size_t)bh * SS * DK;
    const float* Vh = g_V + (size_t)bh * SS * DK;
    const int* maskb = mask + (size_t)b * SS * SS;

    __shared__ float Qs[64][64];   // [d][q]  16KB
    __shared__ float Ks[64][32];   // [d][k]   8KB
    __shared__ float Vs[32][64];   // [k][d]   8KB
    __shared__ float Sc[64][36];   // [q][k] padded  9.2KB

    const int tid = threadIdx.x;

    // Load Q tile transposed: Qs[d][q]
    #pragma unroll
    for (int it = 0; it < 4; ++it) {
        const int linear = tid + it*256;  // 0..1023 float4 slots
        const int d4 = linear >> 6;       // 0..15
        const int q  = linear & 63;
        float4 v = *(const float4*)&Qh[(size_t)(q0 + q) * DK + d4*4];
        Qs[d4*4+0][q] = v.x; Qs[d4*4+1][q] = v.y;
        Qs[d4*4+2][q] = v.z; Qs[d4*4+3][q] = v.w;
    }

    const int tx1 = tid & 7,  ty1 = tid >> 3;   // stage1: 2q x 4k
    const int tx2 = tid & 15, ty2 = tid >> 4;   // stage2: 4q x 4d

    u64 acc[4][2] = {};   // 4 q-rows x 2 d-pairs (stage2 accumulators)

    for (int k0 = 0; k0 < SS; k0 += 32) {
        __syncthreads();  // prior stage2 done with Ks/Vs/Sc; also covers Qs fill (first iter)
        // Load K chunk transposed: Ks[d][k]
        #pragma unroll
        for (int it = 0; it < 2; ++it) {
            const int linear = tid + it*256;   // 0..511
            const int d4 = linear >> 5;        // 0..15
            const int kr = linear & 31;
            float4 v = *(const float4*)&Kh[(size_t)(k0 + kr) * DK + d4*4];
            Ks[d4*4+0][kr] = v.x; Ks[d4*4+1][kr] = v.y;
            Ks[d4*4+2][kr] = v.z; Ks[d4*4+3][kr] = v.w;
        }
        // Load V chunk row-major: Vs[k][d]
        #pragma unroll
        for (int it = 0; it < 2; ++it) {
            const int linear = tid + it*256;
            const int kr = linear >> 4;
            const int d4 = linear & 15;
            *(float4*)&Vs[kr][d4*4] = *(const float4*)&Vh[(size_t)(k0 + kr) * DK + d4*4];
        }
        __syncthreads();

        // Stage 1: Sc[q][k] = (Q . K)/8, masked   (2q x 4k per thread, f32x2)
        {
            u64 s0[2] = {}, s1[2] = {};
            #pragma unroll
            for (int kk = 0; kk < 64; ++kk) {
                float2 av = *(const float2*)&Qs[kk][ty1*2];
                const u64* kp = (const u64*)&Ks[kk][tx1*4];
                u64 b0 = kp[0], b1 = kp[1];
                u64 ax = bcast2(av.x), ay = bcast2(av.y);
                fma2(s0[0], ax, b0); fma2(s0[1], ax, b1);
                fma2(s1[0], ay, b0); fma2(s1[1], ay, b1);
            }
            float2 u00 = unpack2(s0[0]), u01 = unpack2(s0[1]);
            float2 u10 = unpack2(s1[0]), u11 = unpack2(s1[1]);
            const size_t mrow0 = (size_t)(q0 + ty1*2 + 0) * SS + k0 + tx1*4;
            const size_t mrow1 = (size_t)(q0 + ty1*2 + 1) * SS + k0 + tx1*4;
            float4 o0, o1;
            o0.x = (maskb[mrow0+0]==0) ? -1e9f : u00.x*0.125f;
            o0.y = (maskb[mrow0+1]==0) ? -1e9f : u00.y*0.125f;
            o0.z = (maskb[mrow0+2]==0) ? -1e9f : u01.x*0.125f;
            o0.w = (maskb[mrow0+3]==0) ? -1e9f : u01.y*0.125f;
            o1.x = (maskb[mrow1+0]==0) ? -1e9f : u10.x*0.125f;
            o1.y = (maskb[mrow1+1]==0) ? -1e9f : u10.y*0.125f;
            o1.z = (maskb[mrow1+2]==0) ? -1e9f : u11.x*0.125f;
            o1.w = (maskb[mrow1+3]==0) ? -1e9f : u11.y*0.125f;
            *(float4*)&Sc[ty1*2+0][tx1*4] = o0;
            *(float4*)&Sc[ty1*2+1][tx1*4] = o1;
        }
        __syncthreads();

        // Stage 2: acc += Sc @ Vs   (4q x 4d per thread, f32x2)
        #pragma unroll
        for (int kc = 0; kc < 32; ++kc) {
            float a0 = Sc[ty2*4+0][kc];
            float a1 = Sc[ty2*4+1][kc];
            float a2 = Sc[ty2*4+2][kc];
            float a3 = Sc[ty2*4+3][kc];
            const u64* vp = (const u64*)&Vs[kc][tx2*4];
            u64 v0 = vp[0], v1 = vp[1];
            fma2(acc[0][0], bcast2(a0), v0); fma2(acc[0][1], bcast2(a0), v1);
            fma2(acc[1][0], bcast2(a1), v0); fma2(acc[1][1], bcast2(a1), v1);
            fma2(acc[2][0], bcast2(a2), v0); fma2(acc[2][1], bcast2(a2), v1);
            fma2(acc[3][0], bcast2(a3), v0); fma2(acc[3][1], bcast2(a3), v1);
        }
    }

    // Softmax over the 64-wide d dimension: each row held by 16 lanes (tx2),
    // each lane has 4 of 64 values. Reduce with width-16 shuffles.
    #pragma unroll
    for (int i = 0; i < 4; ++i) {
        float2 pa = unpack2(acc[i][0]);
        float2 pb = unpack2(acc[i][1]);
        float v0 = pa.x, v1 = pa.y, v2 = pb.x, v3 = pb.y;
        float m = fmaxf(fmaxf(v0, v1), fmaxf(v2, v3));
        #pragma unroll
        for (int off = 8; off >= 1; off >>= 1)
            m = fmaxf(m, __shfl_xor_sync(0xffffffffu, m, off, 16));
        float e0 = __expf(v0 - m);
        float e1 = __expf(v1 - m);
        float e2 = __expf(v2 - m);
        float e3 = __expf(v3 - m);
        float sum = e0 + e1 + e2 + e3;
        #pragma unroll
        for (int off = 8; off >= 1; off >>= 1)
            sum += __shfl_xor_sync(0xffffffffu, sum, off, 16);
        const float inv = 1.0f / sum;
        float4 o = { e0*inv, e1*inv, e2*inv, e3*inv };
        const int s = q0 + ty2*4 + i;
        const int col = h * DK + tx2*4;
        *(float4*)&X[((size_t)b * SS + s) * DD + col] = o;
    }
}

// ---------------------------------------------------------------------------
// Launch
// ---------------------------------------------------------------------------
extern "C" void kernel_launch(void* const* d_in, const int* in_sizes, int n_in,
                              void* d_out, int out_size)
{
    (void)in_sizes; (void)n_in; (void)out_size;
    const float* k_in = (const float*)d_in[0];
    const float* q_in = (const float*)d_in[1];
    const float* v_in = (const float*)d_in[2];
    const int*   mask = (const int*)  d_in[3];
    const float* Wq = (const float*)d_in[4];
    const float* bq = (const float*)d_in[5];
    const float* Wk = (const float*)d_in[6];
    const float* bk = (const float*)d_in[7];
    const float* Wv = (const float*)d_in[8];
    const float* bv = (const float*)d_in[9];
    const float* Wo = (const float*)d_in[10];
    const float* bo = (const float*)d_in[11];
    float* out = (float*)d_out;

    float *pQ, *pK, *pV, *pX;
    cudaGetSymbolAddress((void**)&pQ, g_Q);
    cudaGetSymbolAddress((void**)&pK, g_K);
    cudaGetSymbolAddress((void**)&pV, g_V);
    cudaGetSymbolAddress((void**)&pX, g_X);

    dim3 ggemm(DD/128, BSM/128);   // 8 x 32
    gemm_nt_kernel<true><<<ggemm, 256>>>(q_in, Wq, bq, pQ);
    gemm_nt_kernel<true><<<ggemm, 256>>>(k_in, Wk, bk, pK);
    gemm_nt_kernel<true><<<ggemm, 256>>>(v_in, Wv, bv, pV);

    dim3 gattn(SS/64, BB*HH);      // 32 x 32
    attn_kernel<<<gattn, 256>>>(mask, pX);

    gemm_nt_kernel<false><<<ggemm, 256>>>(pX, Wo, bo, out);
}

// round 3
// speedup vs baseline: 2.4487x; 2.2221x over previous
#include <cuda_runtime.h>
#include <cstddef>

// Problem constants
#define BB 2
#define SS 2048
#define DD 1024
#define HH 16
#define DK 64
#define BSM (BB*SS)          // 4096 rows for the projection GEMMs

typedef unsigned long long u64;

// Scratch (device globals; allocation-free per harness rules).
__device__ float g_Q[(size_t)BB*HH*SS*DK];
__device__ float g_K[(size_t)BB*HH*SS*DK];
__device__ float g_V[(size_t)BB*HH*SS*DK];
__device__ float g_X[(size_t)BB*SS*DD];
__device__ float g_Tp[(size_t)4*32*64*64];   // K^T V partials: [split][bh][d1][d2]
__device__ int   g_mflag[2*32*32];           // [b][qtile][ktile] has-zero flags

// ---------------------------------------------------------------------------
// Packed fp32x2 helpers
// ---------------------------------------------------------------------------
__device__ __forceinline__ u64 pack2(float lo, float hi) {
    u64 r;
    asm("mov.b64 %0, {%1, %2};" : "=l"(r)
        : "r"(__float_as_uint(lo)), "r"(__float_as_uint(hi)));
    return r;
}
__device__ __forceinline__ u64 bcast2(float x) { return pack2(x, x); }
__device__ __forceinline__ void fma2(u64 &d, u64 a, u64 b) {
    asm("fma.rn.f32x2 %0, %1, %2, %0;" : "+l"(d) : "l"(a), "l"(b));
}
__device__ __forceinline__ float2 unpack2(u64 v) {
    unsigned lo, hi;
    asm("mov.b64 {%0, %1}, %2;" : "=r"(lo), "=r"(hi) : "l"(v));
    return make_float2(__uint_as_float(lo), __uint_as_float(hi));
}

// ---------------------------------------------------------------------------
// GEMM-NT: Dst[m,n] = sum_k A[m,k] * W[n,k] + Bias[n]
// 128x128 tile, K-tile 16, 256 threads, 8x8 micro in f32x2, double-buffered.
// ---------------------------------------------------------------------------
template<bool SPLIT>
__global__ __launch_bounds__(256, 2)
void gemm_nt_kernel(const float* __restrict__ A,
                    const float* __restrict__ W,
                    const float* __restrict__ Bias,
                    float* __restrict__ Dst)
{
    const int m0 = blockIdx.y * 128;
    const int n0 = blockIdx.x * 128;

    __shared__ float As[2][16][128];
    __shared__ float Bs[2][16][128];

    const int tid = threadIdx.x;
    const int tx  = tid & 15;
    const int ty  = tid >> 4;

    const int r0 = tid >> 2;
    const int r1 = r0 + 64;
    const int c4 = (tid & 3) * 4;

    const float* pA0 = A + (size_t)(m0 + r0) * DD + c4;
    const float* pA1 = A + (size_t)(m0 + r1) * DD + c4;
    const float* pW0 = W + (size_t)(n0 + r0) * DD + c4;
    const float* pW1 = W + (size_t)(n0 + r1) * DD + c4;

    float4 ra0 = *(const float4*)(pA0);
    float4 ra1 = *(const float4*)(pA1);
    float4 rb0 = *(const float4*)(pW0);
    float4 rb1 = *(const float4*)(pW1);

    As[0][c4+0][r0] = ra0.x; As[0][c4+1][r0] = ra0.y; As[0][c4+2][r0] = ra0.z; As[0][c4+3][r0] = ra0.w;
    As[0][c4+0][r1] = ra1.x; As[0][c4+1][r1] = ra1.y; As[0][c4+2][r1] = ra1.z; As[0][c4+3][r1] = ra1.w;
    Bs[0][c4+0][r0] = rb0.x; Bs[0][c4+1][r0] = rb0.y; Bs[0][c4+2][r0] = rb0.z; Bs[0][c4+3][r0] = rb0.w;
    Bs[0][c4+0][r1] = rb1.x; Bs[0][c4+1][r1] = rb1.y; Bs[0][c4+2][r1] = rb1.z; Bs[0][c4+3][r1] = rb1.w;
    __syncthreads();

    u64 acc[8][4] = {};

    int cur = 0;
    for (int t = 0; t < 64; ++t) {
        if (t < 63) {
            const int off = (t + 1) * 16;
            ra0 = *(const float4*)(pA0 + off);
            ra1 = *(const float4*)(pA1 + off);
            rb0 = *(const float4*)(pW0 + off);
            rb1 = *(const float4*)(pW1 + off);
        }
        #pragma unroll
        for (int kk = 0; kk < 16; ++kk) {
            float4 a0 = *(const float4*)&As[cur][kk][ty*8];
            float4 a1 = *(const float4*)&As[cur][kk][ty*8 + 4];
            const u64* bp = (const u64*)&Bs[cur][kk][tx*8];
            u64 b0 = bp[0], b1 = bp[1], b2 = bp[2], b3 = bp[3];
            u64 az[8];
            az[0] = bcast2(a0.x); az[1] = bcast2(a0.y);
            az[2] = bcast2(a0.z); az[3] = bcast2(a0.w);
            az[4] = bcast2(a1.x); az[5] = bcast2(a1.y);
            az[6] = bcast2(a1.z); az[7] = bcast2(a1.w);
            #pragma unroll
            for (int i = 0; i < 8; ++i) {
                fma2(acc[i][0], az[i], b0);
                fma2(acc[i][1], az[i], b1);
                fma2(acc[i][2], az[i], b2);
                fma2(acc[i][3], az[i], b3);
            }
        }
        if (t < 63) {
            const int nxt = cur ^ 1;
            As[nxt][c4+0][r0] = ra0.x; As[nxt][c4+1][r0] = ra0.y; As[nxt][c4+2][r0] = ra0.z; As[nxt][c4+3][r0] = ra0.w;
            As[nxt][c4+0][r1] = ra1.x; As[nxt][c4+1][r1] = ra1.y; As[nxt][c4+2][r1] = ra1.z; As[nxt][c4+3][r1] = ra1.w;
            Bs[nxt][c4+0][r0] = rb0.x; Bs[nxt][c4+1][r0] = rb0.y; Bs[nxt][c4+2][r0] = rb0.z; Bs[nxt][c4+3][r0] = rb0.w;
            Bs[nxt][c4+0][r1] = rb1.x; Bs[nxt][c4+1][r1] = rb1.y; Bs[nxt][c4+2][r1] = rb1.z; Bs[nxt][c4+3][r1] = rb1.w;
            __syncthreads();
            cur = nxt;
        }
    }

    const int nb = n0 + tx * 8;
    const float4 bb0 = *(const float4*)&Bias[nb];
    const float4 bb1 = *(const float4*)&Bias[nb + 4];
    #pragma unroll
    for (int i = 0; i < 8; ++i) {
        const int m = m0 + ty * 8 + i;
        float2 p0 = unpack2(acc[i][0]);
        float2 p1 = unpack2(acc[i][1]);
        float2 p2 = unpack2(acc[i][2]);
        float2 p3 = unpack2(acc[i][3]);
        float4 o0 = { p0.x + bb0.x, p0.y + bb0.y, p1.x + bb0.z, p1.y + bb0.w };
        float4 o1 = { p2.x + bb1.x, p2.y + bb1.y, p3.x + bb1.z, p3.y + bb1.w };
        if (SPLIT) {
            const int b  = m >> 11;
            const int s  = m & (SS - 1);
            const int h  = nb >> 6;
            const int dk = nb & 63;
            float* dst = Dst + (((size_t)(b*HH + h) * SS + s) * DK + dk);
            *(float4*)dst       = o0;
            *(float4*)(dst + 4) = o1;
        } else {
            float* dst = Dst + (size_t)m * DD + nb;
            *(float4*)dst       = o0;
            *(float4*)(dst + 4) = o1;
        }
    }
}

// ---------------------------------------------------------------------------
// Stage A: T_partial[sp][bh] = sum_{s in split} K[bh][s][:]^T V[bh][s][:]
// Grid (bh=32, sp=4), 256 threads, 4x4 micro in f32x2.
// ---------------------------------------------------------------------------
__global__ __launch_bounds__(256)
void kv_outer_kernel()
{
    const int bh = blockIdx.x;
    const int sp = blockIdx.y;
    const float* Kh = g_K + (size_t)bh * SS * DK;
    const float* Vh = g_V + (size_t)bh * SS * DK;

    __shared__ float Ks[32][68];
    __shared__ float Vs[32][68];

    const int tid = threadIdx.x;
    const int tx = tid & 15;     // d2 group
    const int ty = tid >> 4;     // d1 group

    u64 acc[4][2] = {};
    const int s0 = sp * 512;

    for (int c = 0; c < 512; c += 32) {
        __syncthreads();
        #pragma unroll
        for (int it = 0; it < 2; ++it) {
            const int lin = tid + it * 256;   // 0..511
            const int r  = lin >> 4;          // 0..31
            const int c4 = (lin & 15) * 4;
            *(float4*)&Ks[r][c4] = *(const float4*)&Kh[(size_t)(s0 + c + r) * DK + c4];
            *(float4*)&Vs[r][c4] = *(const float4*)&Vh[(size_t)(s0 + c + r) * DK + c4];
        }
        __syncthreads();
        #pragma unroll
        for (int s = 0; s < 32; ++s) {
            float4 a = *(const float4*)&Ks[s][ty*4];
            const u64* vp = (const u64*)&Vs[s][tx*4];
            u64 v0 = vp[0], v1 = vp[1];
            fma2(acc[0][0], bcast2(a.x), v0); fma2(acc[0][1], bcast2(a.x), v1);
            fma2(acc[1][0], bcast2(a.y), v0); fma2(acc[1][1], bcast2(a.y), v1);
            fma2(acc[2][0], bcast2(a.z), v0); fma2(acc[2][1], bcast2(a.z), v1);
            fma2(acc[3][0], bcast2(a.w), v0); fma2(acc[3][1], bcast2(a.w), v1);
        }
    }

    float* dst = g_Tp + (size_t)(sp * 32 + bh) * 64 * 64;
    #pragma unroll
    for (int i = 0; i < 4; ++i) {
        float2 p0 = unpack2(acc[i][0]);
        float2 p1 = unpack2(acc[i][1]);
        float4 o = { p0.x, p0.y, p1.x, p1.y };
        *(float4*)&dst[(ty*4 + i) * 64 + tx*4] = o;
    }
}

// ---------------------------------------------------------------------------
// Mask scan: flag each 64x64 mask tile containing any zero.
// Grid (kt=32, qt=32, b=2), 256 threads.
// ---------------------------------------------------------------------------
__global__ __launch_bounds__(256)
void mask_scan_kernel(const int* __restrict__ mask)
{
    const int kt = blockIdx.x, qt = blockIdx.y, b = blockIdx.z;
    const int* mp = mask + (size_t)b * SS * SS + (size_t)qt * 64 * SS + kt * 64;
    __shared__ int s_bad;
    if (threadIdx.x == 0) s_bad = 0;
    __syncthreads();
    const int r  = threadIdx.x >> 2;
    const int c0 = (threadIdx.x & 3) * 16;
    bool bad = false;
    #pragma unroll
    for (int j = 0; j < 4; ++j) {
        int4 v = *(const int4*)&mp[(size_t)r * SS + c0 + j*4];
        if (v.x == 0 || v.y == 0 || v.z == 0 || v.w == 0) bad = true;
    }
    if (bad) s_bad = 1;
    __syncthreads();
    if (threadIdx.x == 0) g_mflag[(b*32 + qt)*32 + kt] = s_bad;
}

// ---------------------------------------------------------------------------
// Stage B: qkv = Q @ T / 8 (+ mask corrections), softmax over DK, write X.
// Grid (qt=32, bh=32), 256 threads.
// ---------------------------------------------------------------------------
__global__ __launch_bounds__(256)
void qt_softmax_kernel(const int* __restrict__ mask, float* __restrict__ X)
{
    const int qt = blockIdx.x;
    const int bh = blockIdx.y;
    const int b  = bh >> 4;
    const int h  = bh & (HH - 1);
    const int q0 = qt * 64;

    const float* Qh = g_Q + (size_t)bh * SS * DK;

    __shared__ float Qs[64][68];   // [d1][q]
    __shared__ float Ts[64][68];   // [d1][d2] (already * 0.125)
    __shared__ float CK[16][68];
    __shared__ float CV[16][68];
    __shared__ int s_flags[32];
    __shared__ int s_any;

    const int tid = threadIdx.x;

    // Load Q tile transposed: Qs[d][q]
    #pragma unroll
    for (int it = 0; it < 4; ++it) {
        const int lin = tid + it * 256;
        const int d4 = lin >> 6;
        const int q  = lin & 63;
        float4 v = *(const float4*)&Qh[(size_t)(q0 + q) * DK + d4*4];
        Qs[d4*4+0][q] = v.x; Qs[d4*4+1][q] = v.y;
        Qs[d4*4+2][q] = v.z; Qs[d4*4+3][q] = v.w;
    }

    // Load T = (sum of 4 partials) * 0.125
    {
        const float* T0 = g_Tp + (size_t)(0*32 + bh) * 4096;
        const float* T1 = g_Tp + (size_t)(1*32 + bh) * 4096;
        const float* T2 = g_Tp + (size_t)(2*32 + bh) * 4096;
        const float* T3 = g_Tp + (size_t)(3*32 + bh) * 4096;
        #pragma unroll
        for (int it = 0; it < 4; ++it) {
            const int lin = tid + it * 256;   // 0..1023 float4 slots
            const int d1 = lin >> 4;
            const int c4 = (lin & 15) * 4;
            const int off = d1 * 64 + c4;
            float4 a = *(const float4*)(T0 + off);
            float4 bb = *(const float4*)(T1 + off);
            float4 cc = *(const float4*)(T2 + off);
            float4 dd = *(const float4*)(T3 + off);
            float4 o = { (a.x+bb.x+cc.x+dd.x)*0.125f, (a.y+bb.y+cc.y+dd.y)*0.125f,
                         (a.z+bb.z+cc.z+dd.z)*0.125f, (a.w+bb.w+cc.w+dd.w)*0.125f };
            *(float4*)&Ts[d1][c4] = o;
        }
    }

    // Load flags
    if (tid == 0) s_any = 0;
    __syncthreads();
    if (tid < 32) {
        int f = g_mflag[(b*32 + qt)*32 + tid];
        s_flags[tid] = f;
        if (f) s_any = 1;
    }
    __syncthreads();

    const int tx = tid & 15;     // d2 group
    const int ty = tid >> 4;     // q group

    // qkv = Qs^T @ Ts   (4q x 4d2 per thread)
    u64 acc[4][2] = {};
    #pragma unroll
    for (int d1 = 0; d1 < 64; ++d1) {
        float4 a = *(const float4*)&Qs[d1][ty*4];
        const u64* tp = (const u64*)&Ts[d1][tx*4];
        u64 t0 = tp[0], t1 = tp[1];
        fma2(acc[0][0], bcast2(a.x), t0); fma2(acc[0][1], bcast2(a.x), t1);
        fma2(acc[1][0], bcast2(a.y), t0); fma2(acc[1][1], bcast2(a.y), t1);
        fma2(acc[2][0], bcast2(a.z), t0); fma2(acc[2][1], bcast2(a.z), t1);
        fma2(acc[3][0], bcast2(a.w), t0); fma2(acc[3][1], bcast2(a.w), t1);
    }

    // Correction path for mask tiles containing zeros (exact; rarely taken)
    if (s_any) {
        const float* Kh = g_K + (size_t)bh * SS * DK;
        const float* Vh = g_V + (size_t)bh * SS * DK;
        const int* mb = mask + (size_t)b * SS * SS;
        for (int kt = 0; kt < 32; ++kt) {
            if (!s_flags[kt]) continue;
            for (int sub = 0; sub < 4; ++sub) {
                const int kbase = kt*64 + sub*16;
                __syncthreads();
                {
                    const int r  = tid >> 4;
                    const int c4 = (tid & 15) * 4;
                    *(float4*)&CK[r][c4] = *(const float4*)&Kh[(size_t)(kbase + r) * DK + c4];
                    *(float4*)&CV[r][c4] = *(const float4*)&Vh[(size_t)(kbase + r) * DK + c4];
                }
                __syncthreads();
                for (int kk = 0; kk < 16; ++kk) {
                    const u64* vp = (const u64*)&CV[kk][tx*4];
                    u64 v0 = vp[0], v1 = vp[1];
                    #pragma unroll
                    for (int qi = 0; qi < 4; ++qi) {
                        const int q = q0 + ty*4 + qi;
                        if (mb[(size_t)q * SS + kbase + kk] == 0) {
                            float s = 0.f;
                            for (int d1 = 0; d1 < 64; ++d1)
                                s += Qs[d1][ty*4 + qi] * CK[kk][d1];
                            const float coef = -1e9f - s * 0.125f;
                            u64 cz = bcast2(coef);
                            fma2(acc[qi][0], cz, v0);
                            fma2(acc[qi][1], cz, v1);
                        }
                    }
                }
            }
        }
    }

    // Softmax over d2 (row of 64 spread across 16 tx lanes x 4 values)
    #pragma unroll
    for (int i = 0; i < 4; ++i) {
        float2 pa = unpack2(acc[i][0]);
        float2 pb = unpack2(acc[i][1]);
        float v0 = pa.x, v1 = pa.y, v2 = pb.x, v3 = pb.y;
        float m = fmaxf(fmaxf(v0, v1), fmaxf(v2, v3));
        #pragma unroll
        for (int off = 8; off >= 1; off >>= 1)
            m = fmaxf(m, __shfl_xor_sync(0xffffffffu, m, off, 16));
        float e0 = __expf(v0 - m);
        float e1 = __expf(v1 - m);
        float e2 = __expf(v2 - m);
        float e3 = __expf(v3 - m);
        float sum = e0 + e1 + e2 + e3;
        #pragma unroll
        for (int off = 8; off >= 1; off >>= 1)
            sum += __shfl_xor_sync(0xffffffffu, sum, off, 16);
        const float inv = 1.0f / sum;
        float4 o = { e0*inv, e1*inv, e2*inv, e3*inv };
        const int s = q0 + ty*4 + i;
        const int col = h * DK + tx*4;
        *(float4*)&X[((size_t)b * SS + s) * DD + col] = o;
    }
}

// ---------------------------------------------------------------------------
// Launch
// ---------------------------------------------------------------------------
extern "C" void kernel_launch(void* const* d_in, const int* in_sizes, int n_in,
                              void* d_out, int out_size)
{
    (void)in_sizes; (void)n_in; (void)out_size;
    const float* k_in = (const float*)d_in[0];
    const float* q_in = (const float*)d_in[1];
    const float* v_in = (const float*)d_in[2];
    const int*   mask = (const int*)  d_in[3];
    const float* Wq = (const float*)d_in[4];
    const float* bq = (const float*)d_in[5];
    const float* Wk = (const float*)d_in[6];
    const float* bk = (const float*)d_in[7];
    const float* Wv = (const float*)d_in[8];
    const float* bv = (const float*)d_in[9];
    const float* Wo = (const float*)d_in[10];
    const float* bo = (const float*)d_in[11];
    float* out = (float*)d_out;

    float *pQ, *pK, *pV, *pX;
    cudaGetSymbolAddress((void**)&pQ, g_Q);
    cudaGetSymbolAddress((void**)&pK, g_K);
    cudaGetSymbolAddress((void**)&pV, g_V);
    cudaGetSymbolAddress((void**)&pX, g_X);

    dim3 ggemm(DD/128, BSM/128);   // 8 x 32
    gemm_nt_kernel<true><<<ggemm, 256>>>(q_in, Wq, bq, pQ);
    gemm_nt_kernel<true><<<ggemm, 256>>>(k_in, Wk, bk, pK);
    gemm_nt_kernel<true><<<ggemm, 256>>>(v_in, Wv, bv, pV);

    kv_outer_kernel<<<dim3(32, 4), 256>>>();
    mask_scan_kernel<<<dim3(32, 32, 2), 256>>>(mask);
    qt_softmax_kernel<<<dim3(32, 32), 256>>>(mask, pX);

    gemm_nt_kernel<false><<<ggemm, 256>>>(pX, Wo, bo, out);
}

// round 5
// speedup vs baseline: 4.6402x; 1.8949x over previous
#include <cuda_runtime.h>
#include <cuda_bf16.h>
#include <cstddef>
#include <cstdint>

// Problem constants
#define BB 2
#define SS 2048
#define DD 1024
#define HH 16
#define DK 64
#define BSM (BB*SS)          // 4096 rows for the projection GEMMs

typedef unsigned long long u64;

// Scratch (device globals; allocation-free per harness rules).
__device__ float g_Q[(size_t)BB*HH*SS*DK];
__device__ float g_K[(size_t)BB*HH*SS*DK];
__device__ float g_V[(size_t)BB*HH*SS*DK];
__device__ float g_X[(size_t)BB*SS*DD];
__device__ float g_Tp[(size_t)4*32*64*64];   // K^T V partials
__device__ int   g_mflag[2*32*32];           // mask-tile has-zero flags
// split-bf16 operand scratch (reused sequentially across the 4 GEMMs)
__device__ __nv_bfloat16 g_Ahi[(size_t)BSM*DD];
__device__ __nv_bfloat16 g_Alo[(size_t)BSM*DD];
__device__ __nv_bfloat16 g_Bhi[(size_t)DD*DD];
__device__ __nv_bfloat16 g_Blo[(size_t)DD*DD];

// ---------------------------------------------------------------------------
// Packed fp32x2 helpers (attention-side kernels)
// ---------------------------------------------------------------------------
__device__ __forceinline__ u64 pack2(float lo, float hi) {
    u64 r;
    asm("mov.b64 %0, {%1, %2};" : "=l"(r)
        : "r"(__float_as_uint(lo)), "r"(__float_as_uint(hi)));
    return r;
}
__device__ __forceinline__ u64 bcast2(float x) { return pack2(x, x); }
__device__ __forceinline__ void fma2(u64 &d, u64 a, u64 b) {
    asm("fma.rn.f32x2 %0, %1, %2, %0;" : "+l"(d) : "l"(a), "l"(b));
}
__device__ __forceinline__ float2 unpack2(u64 v) {
    unsigned lo, hi;
    asm("mov.b64 {%0, %1}, %2;" : "=r"(lo), "=r"(hi) : "l"(v));
    return make_float2(__uint_as_float(lo), __uint_as_float(hi));
}

// ---------------------------------------------------------------------------
// Warp-MMA helpers (baseline PTX, legal on non-'a' sm_103 target)
// ---------------------------------------------------------------------------
__device__ __forceinline__ uint32_t smem_u32(const void* p) {
    uint32_t a;
    asm("{ .reg .u64 t; cvta.to.shared.u64 t, %1; cvt.u32.u64 %0, t; }"
        : "=r"(a) : "l"(p));
    return a;
}
__device__ __forceinline__ void ldsm_x4(uint32_t* r, uint32_t addr) {
    asm volatile("ldmatrix.sync.aligned.m8n8.x4.shared.b16 {%0,%1,%2,%3}, [%4];"
        : "=r"(r[0]), "=r"(r[1]), "=r"(r[2]), "=r"(r[3]) : "r"(addr));
}
__device__ __forceinline__ void mma_bf16(float* d, const uint32_t* a, const uint32_t* b) {
    asm volatile("mma.sync.aligned.m16n8k16.row.col.f32.bf16.bf16.f32 "
        "{%0,%1,%2,%3}, {%4,%5,%6,%7}, {%8,%9}, {%0,%1,%2,%3};"
        : "+f"(d[0]), "+f"(d[1]), "+f"(d[2]), "+f"(d[3])
        : "r"(a[0]), "r"(a[1]), "r"(a[2]), "r"(a[3]), "r"(b[0]), "r"(b[1]));
}
__device__ __forceinline__ void cp16(uint32_t dst, const void* src) {
    asm volatile("cp.async.cg.shared.global [%0], [%1], 16;" :: "r"(dst), "l"(src));
}
#define CP_COMMIT() asm volatile("cp.async.commit_group;")
#define CP_WAIT(n)  asm volatile("cp.async.wait_group %0;" :: "n"(n))

// smem geometry for the MMA GEMM: 4 tiles (Ah,Al,Wh,Wl) of 128 x 32 bf16,
// row stride 40 bf16 (80B, LDSM conflict-free), double buffered.
#define TSTRIDE_B 80
#define TILE_B    (128*TSTRIDE_B)        // 10240
#define BUF_B     (4*TILE_B)             // 40960
#define SMEM_GEMM (2*BUF_B)              // 81920

// ---------------------------------------------------------------------------
// Split-bf16 conversion: src fp32 -> hi/lo bf16 (a ~= hi + lo)
// ---------------------------------------------------------------------------
__global__ __launch_bounds__(256)
void split_bf16_kernel(const float* __restrict__ src,
                       __nv_bfloat16* __restrict__ hi,
                       __nv_bfloat16* __restrict__ lo, int n4)
{
    int i = blockIdx.x * blockDim.x + threadIdx.x;
    if (i >= n4) return;
    float4 v = ((const float4*)src)[i];
    __nv_bfloat16 h0 = __float2bfloat16(v.x);
    __nv_bfloat16 h1 = __float2bfloat16(v.y);
    __nv_bfloat16 h2 = __float2bfloat16(v.z);
    __nv_bfloat16 h3 = __float2bfloat16(v.w);
    __nv_bfloat16 l0 = __float2bfloat16(v.x - __bfloat162float(h0));
    __nv_bfloat16 l1 = __float2bfloat16(v.y - __bfloat162float(h1));
    __nv_bfloat16 l2 = __float2bfloat16(v.z - __bfloat162float(h2));
    __nv_bfloat16 l3 = __float2bfloat16(v.w - __bfloat162float(h3));
    ((__nv_bfloat162*)hi)[2*i + 0] = __halves2bfloat162(h0, h1);
    ((__nv_bfloat162*)hi)[2*i + 1] = __halves2bfloat162(h2, h3);
    ((__nv_bfloat162*)lo)[2*i + 0] = __halves2bfloat162(l0, l1);
    ((__nv_bfloat162*)lo)[2*i + 1] = __halves2bfloat162(l2, l3);
}

// ---------------------------------------------------------------------------
// mma.sync GEMM-NT: Dst[m,n] = sum_k A[m,k]*W[n,k] + Bias[n], split-bf16 x4.
// Tile 128x128, BK=32, 256 threads (8 warps: 4m x 2n, warp tile 32x64).
// cp.async double-buffered. SPLIT -> head-split output layout.
// ---------------------------------------------------------------------------
template<bool SPLIT>
__global__ __launch_bounds__(256, 2)
void gemm_mma_kernel(const __nv_bfloat16* __restrict__ Ahi,
                     const __nv_bfloat16* __restrict__ Alo,
                     const __nv_bfloat16* __restrict__ Bhi,
                     const __nv_bfloat16* __restrict__ Blo,
                     const float* __restrict__ Bias,
                     float* __restrict__ Dst)
{
    extern __shared__ char smem[];
    const int tid  = threadIdx.x;
    const int wid  = tid >> 5;
    const int lane = tid & 31;
    const int bm = blockIdx.y * 128;
    const int bn = blockIdx.x * 128;

    const uint32_t sA = smem_u32(smem);

    const char* gT[4] = {
        (const char*)Ahi + (size_t)bm * 2048,
        (const char*)Alo + (size_t)bm * 2048,
        (const char*)Bhi + (size_t)bn * 2048,
        (const char*)Blo + (size_t)bn * 2048
    };

    const int cr = tid >> 2;        // 0..63
    const int cc = (tid & 3) * 16;  // byte col within 64B chunk row

    // stage chunk ck into buffer buf
    #define STAGE(buf, ck) do {                                              \
        const int kb = (ck) * 64;                                            \
        _Pragma("unroll")                                                    \
        for (int t = 0; t < 4; ++t) {                                        \
            const char* s0 = gT[t] + (size_t)cr * 2048 + kb + cc;            \
            uint32_t d0 = sA + (buf)*BUF_B + t*TILE_B + cr*TSTRIDE_B + cc;   \
            cp16(d0, s0);                                                    \
            cp16(d0 + 64*TSTRIDE_B, s0 + (size_t)64*2048);                   \
        }                                                                    \
    } while (0)

    const int wm = (wid >> 1) * 32;
    const int wn = (wid & 1) * 64;

    // lane-dependent ldmatrix address pieces
    const int laA_row = lane & 15;
    const int laA_k   = (lane >> 4) << 3;         // +0 / +8 k
    const int laB_row = ((lane >> 4) << 3) + (lane & 7);
    const int laB_k   = ((lane >> 3) & 1) << 3;   // +0 / +8 k

    float acc[2][8][4] = {};

    STAGE(0, 0);
    CP_COMMIT();

    for (int ck = 0; ck < 32; ++ck) {
        const int buf = ck & 1;
        if (ck + 1 < 32) {
            STAGE(buf ^ 1, ck + 1);
            CP_COMMIT();
            CP_WAIT(1);
        } else {
            CP_WAIT(0);
        }
        __syncthreads();

        const uint32_t tAh = sA + buf*BUF_B + 0*TILE_B;
        const uint32_t tAl = sA + buf*BUF_B + 1*TILE_B;
        const uint32_t tWh = sA + buf*BUF_B + 2*TILE_B;
        const uint32_t tWl = sA + buf*BUF_B + 3*TILE_B;

        #pragma unroll
        for (int ks = 0; ks < 32; ks += 16) {
            uint32_t a_h[2][4], a_l[2][4];
            #pragma unroll
            for (int mi = 0; mi < 2; ++mi) {
                const uint32_t ao = (uint32_t)((wm + mi*16 + laA_row) * TSTRIDE_B
                                               + (ks + laA_k) * 2);
                ldsm_x4(a_h[mi], tAh + ao);
                ldsm_x4(a_l[mi], tAl + ao);
            }
            #pragma unroll
            for (int j = 0; j < 4; ++j) {
                uint32_t b_h[4], b_l[4];
                const uint32_t bo = (uint32_t)((wn + j*16 + laB_row) * TSTRIDE_B
                                               + (ks + laB_k) * 2);
                ldsm_x4(b_h, tWh + bo);
                ldsm_x4(b_l, tWl + bo);
                #pragma unroll
                for (int mi = 0; mi < 2; ++mi) {
                    #pragma unroll
                    for (int sub = 0; sub < 2; ++sub) {
                        float* d = acc[mi][j*2 + sub];
                        mma_bf16(d, a_h[mi], &b_h[sub*2]);
                        mma_bf16(d, a_h[mi], &b_l[sub*2]);
                        mma_bf16(d, a_l[mi], &b_h[sub*2]);
                        mma_bf16(d, a_l[mi], &b_l[sub*2]);
                    }
                }
            }
        }
        __syncthreads();
    }

    // Epilogue: each lane owns rows (r0, r0+8), cols (col, col+1) per frag.
    #pragma unroll
    for (int mi = 0; mi < 2; ++mi) {
        #pragma unroll
        for (int nj = 0; nj < 8; ++nj) {
            const int col = bn + wn + nj*8 + (lane & 3)*2;
            const int r0  = bm + wm + mi*16 + (lane >> 2);
            const float b0 = Bias[col], b1 = Bias[col + 1];
            const float* d = acc[mi][nj];
            float2 o0 = { d[0] + b0, d[1] + b1 };
            float2 o1 = { d[2] + b0, d[3] + b1 };
            if (SPLIT) {
                const int h = col >> 6, dk = col & 63;
                const int bA = r0 >> 11, s0 = r0 & (SS - 1);
                float* p0 = Dst + (((size_t)(bA*HH + h) * SS + s0) * DK + dk);
                *(float2*)p0 = o0;
                const int r1 = r0 + 8;
                const int bB = r1 >> 11, s1 = r1 & (SS - 1);
                float* p1 = Dst + (((size_t)(bB*HH + h) * SS + s1) * DK + dk);
                *(float2*)p1 = o1;
            } else {
                *(float2*)(Dst + (size_t)r0 * DD + col)       = o0;
                *(float2*)(Dst + (size_t)(r0+8) * DD + col)   = o1;
            }
        }
    }
    #undef STAGE
}

// ---------------------------------------------------------------------------
// Stage A: T_partial[sp][bh] = sum_{s in split} K[bh][s][:]^T V[bh][s][:]
// ---------------------------------------------------------------------------
__global__ __launch_bounds__(256)
void kv_outer_kernel()
{
    const int bh = blockIdx.x;
    const int sp = blockIdx.y;
    const float* Kh = g_K + (size_t)bh * SS * DK;
    const float* Vh = g_V + (size_t)bh * SS * DK;

    __shared__ float Ks[32][68];
    __shared__ float Vs[32][68];

    const int tid = threadIdx.x;
    const int tx = tid & 15;
    const int ty = tid >> 4;

    u64 acc[4][2] = {};
    const int s0 = sp * 512;

    for (int c = 0; c < 512; c += 32) {
        __syncthreads();
        #pragma unroll
        for (int it = 0; it < 2; ++it) {
            const int lin = tid + it * 256;
            const int r  = lin >> 4;
            const int c4 = (lin & 15) * 4;
            *(float4*)&Ks[r][c4] = *(const float4*)&Kh[(size_t)(s0 + c + r) * DK + c4];
            *(float4*)&Vs[r][c4] = *(const float4*)&Vh[(size_t)(s0 + c + r) * DK + c4];
        }
        __syncthreads();
        #pragma unroll
        for (int s = 0; s < 32; ++s) {
            float4 a = *(const float4*)&Ks[s][ty*4];
            const u64* vp = (const u64*)&Vs[s][tx*4];
            u64 v0 = vp[0], v1 = vp[1];
            fma2(acc[0][0], bcast2(a.x), v0); fma2(acc[0][1], bcast2(a.x), v1);
            fma2(acc[1][0], bcast2(a.y), v0); fma2(acc[1][1], bcast2(a.y), v1);
            fma2(acc[2][0], bcast2(a.z), v0); fma2(acc[2][1], bcast2(a.z), v1);
            fma2(acc[3][0], bcast2(a.w), v0); fma2(acc[3][1], bcast2(a.w), v1);
        }
    }

    float* dst = g_Tp + (size_t)(sp * 32 + bh) * 64 * 64;
    #pragma unroll
    for (int i = 0; i < 4; ++i) {
        float2 p0 = unpack2(acc[i][0]);
        float2 p1 = unpack2(acc[i][1]);
        float4 o = { p0.x, p0.y, p1.x, p1.y };
        *(float4*)&dst[(ty*4 + i) * 64 + tx*4] = o;
    }
}

// ---------------------------------------------------------------------------
// Mask scan: flag each 64x64 mask tile containing any zero.
// ---------------------------------------------------------------------------
__global__ __launch_bounds__(256)
void mask_scan_kernel(const int* __restrict__ mask)
{
    const int kt = blockIdx.x, qt = blockIdx.y, b = blockIdx.z;
    const int* mp = mask + (size_t)b * SS * SS + (size_t)qt * 64 * SS + kt * 64;
    __shared__ int s_bad;
    if (threadIdx.x == 0) s_bad = 0;
    __syncthreads();
    const int r  = threadIdx.x >> 2;
    const int c0 = (threadIdx.x & 3) * 16;
    bool bad = false;
    #pragma unroll
    for (int j = 0; j < 4; ++j) {
        int4 v = *(const int4*)&mp[(size_t)r * SS + c0 + j*4];
        if (v.x == 0 || v.y == 0 || v.z == 0 || v.w == 0) bad = true;
    }
    if (bad) s_bad = 1;
    __syncthreads();
    if (threadIdx.x == 0) g_mflag[(b*32 + qt)*32 + kt] = s_bad;
}

// ---------------------------------------------------------------------------
// Stage B: qkv = Q @ T / 8 (+ mask corrections), softmax over DK, write X.
// ---------------------------------------------------------------------------
__global__ __launch_bounds__(256)
void qt_softmax_kernel(const int* __restrict__ mask, float* __restrict__ X)
{
    const int qt = blockIdx.x;
    const int bh = blockIdx.y;
    const int b  = bh >> 4;
    const int h  = bh & (HH - 1);
    const int q0 = qt * 64;

    const float* Qh = g_Q + (size_t)bh * SS * DK;

    __shared__ float Qs[64][68];
    __shared__ float Ts[64][68];
    __shared__ float CK[16][68];
    __shared__ float CV[16][68];
    __shared__ int s_flags[32];
    __shared__ int s_any;

    const int tid = threadIdx.x;

    #pragma unroll
    for (int it = 0; it < 4; ++it) {
        const int lin = tid + it * 256;
        const int d4 = lin >> 6;
        const int q  = lin & 63;
        float4 v = *(const float4*)&Qh[(size_t)(q0 + q) * DK + d4*4];
        Qs[d4*4+0][q] = v.x; Qs[d4*4+1][q] = v.y;
        Qs[d4*4+2][q] = v.z; Qs[d4*4+3][q] = v.w;
    }

    {
        const float* T0 = g_Tp + (size_t)(0*32 + bh) * 4096;
        const float* T1 = g_Tp + (size_t)(1*32 + bh) * 4096;
        const float* T2 = g_Tp + (size_t)(2*32 + bh) * 4096;
        const float* T3 = g_Tp + (size_t)(3*32 + bh) * 4096;
        #pragma unroll
        for (int it = 0; it < 4; ++it) {
            const int lin = tid + it * 256;
            const int d1 = lin >> 4;
            const int c4 = (lin & 15) * 4;
            const int off = d1 * 64 + c4;
            float4 a = *(const float4*)(T0 + off);
            float4 bb = *(const float4*)(T1 + off);
            float4 cc = *(const float4*)(T2 + off);
            float4 dd = *(const float4*)(T3 + off);
            float4 o = { (a.x+bb.x+cc.x+dd.x)*0.125f, (a.y+bb.y+cc.y+dd.y)*0.125f,
                         (a.z+bb.z+cc.z+dd.z)*0.125f, (a.w+bb.w+cc.w+dd.w)*0.125f };
            *(float4*)&Ts[d1][c4] = o;
        }
    }

    if (tid == 0) s_any = 0;
    __syncthreads();
    if (tid < 32) {
        int f = g_mflag[(b*32 + qt)*32 + tid];
        s_flags[tid] = f;
        if (f) s_any = 1;
    }
    __syncthreads();

    const int tx = tid & 15;
    const int ty = tid >> 4;

    u64 acc[4][2] = {};
    #pragma unroll
    for (int d1 = 0; d1 < 64; ++d1) {
        float4 a = *(const float4*)&Qs[d1][ty*4];
        const u64* tp = (const u64*)&Ts[d1][tx*4];
        u64 t0 = tp[0], t1 = tp[1];
        fma2(acc[0][0], bcast2(a.x), t0); fma2(acc[0][1], bcast2(a.x), t1);
        fma2(acc[1][0], bcast2(a.y), t0); fma2(acc[1][1], bcast2(a.y), t1);
        fma2(acc[2][0], bcast2(a.z), t0); fma2(acc[2][1], bcast2(a.z), t1);
        fma2(acc[3][0], bcast2(a.w), t0); fma2(acc[3][1], bcast2(a.w), t1);
    }

    if (s_any) {
        const float* Kh = g_K + (size_t)bh * SS * DK;
        const float* Vh = g_V + (size_t)bh * SS * DK;
        const int* mb = mask + (size_t)b * SS * SS;
        for (int kt = 0; kt < 32; ++kt) {
            if (!s_flags[kt]) continue;
            for (int sub = 0; sub < 4; ++sub) {
                const int kbase = kt*64 + sub*16;
                __syncthreads();
                {
                    const int r  = tid >> 4;
                    const int c4 = (tid & 15) * 4;
                    *(float4*)&CK[r][c4] = *(const float4*)&Kh[(size_t)(kbase + r) * DK + c4];
                    *(float4*)&CV[r][c4] = *(const float4*)&Vh[(size_t)(kbase + r) * DK + c4];
                }
                __syncthreads();
                for (int kk = 0; kk < 16; ++kk) {
                    const u64* vp = (const u64*)&CV[kk][tx*4];
                    u64 v0 = vp[0], v1 = vp[1];
                    #pragma unroll
                    for (int qi = 0; qi < 4; ++qi) {
                        const int q = q0 + ty*4 + qi;
                        if (mb[(size_t)q * SS + kbase + kk] == 0) {
                            float s = 0.f;
                            for (int d1 = 0; d1 < 64; ++d1)
                                s += Qs[d1][ty*4 + qi] * CK[kk][d1];
                            const float coef = -1e9f - s * 0.125f;
                            u64 cz = bcast2(coef);
                            fma2(acc[qi][0], cz, v0);
                            fma2(acc[qi][1], cz, v1);
                        }
                    }
                }
            }
        }
    }

    #pragma unroll
    for (int i = 0; i < 4; ++i) {
        float2 pa = unpack2(acc[i][0]);
        float2 pb = unpack2(acc[i][1]);
        float v0 = pa.x, v1 = pa.y, v2 = pb.x, v3 = pb.y;
        float m = fmaxf(fmaxf(v0, v1), fmaxf(v2, v3));
        #pragma unroll
        for (int off = 8; off >= 1; off >>= 1)
            m = fmaxf(m, __shfl_xor_sync(0xffffffffu, m, off, 16));
        float e0 = __expf(v0 - m);
        float e1 = __expf(v1 - m);
        float e2 = __expf(v2 - m);
        float e3 = __expf(v3 - m);
        float sum = e0 + e1 + e2 + e3;
        #pragma unroll
        for (int off = 8; off >= 1; off >>= 1)
            sum += __shfl_xor_sync(0xffffffffu, sum, off, 16);
        const float inv = 1.0f / sum;
        float4 o = { e0*inv, e1*inv, e2*inv, e3*inv };
        const int s = q0 + ty*4 + i;
        const int col = h * DK + tx*4;
        *(float4*)&X[((size_t)b * SS + s) * DD + col] = o;
    }
}

// ---------------------------------------------------------------------------
// Launch
// ---------------------------------------------------------------------------
extern "C" void kernel_launch(void* const* d_in, const int* in_sizes, int n_in,
                              void* d_out, int out_size)
{
    (void)in_sizes; (void)n_in; (void)out_size;
    const float* k_in = (const float*)d_in[0];
    const float* q_in = (const float*)d_in[1];
    const float* v_in = (const float*)d_in[2];
    const int*   mask = (const int*)  d_in[3];
    const float* Wq = (const float*)d_in[4];
    const float* bq = (const float*)d_in[5];
    const float* Wk = (const float*)d_in[6];
    const float* bk = (const float*)d_in[7];
    const float* Wv = (const float*)d_in[8];
    const float* bv = (const float*)d_in[9];
    const float* Wo = (const float*)d_in[10];
    const float* bo = (const float*)d_in[11];
    float* out = (float*)d_out;

    float *pQ, *pK, *pV, *pX;
    __nv_bfloat16 *pAhi, *pAlo, *pBhi, *pBlo;
    cudaGetSymbolAddress((void**)&pQ, g_Q);
    cudaGetSymbolAddress((void**)&pK, g_K);
    cudaGetSymbolAddress((void**)&pV, g_V);
    cudaGetSymbolAddress((void**)&pX, g_X);
    cudaGetSymbolAddress((void**)&pAhi, g_Ahi);
    cudaGetSymbolAddress((void**)&pAlo, g_Alo);
    cudaGetSymbolAddress((void**)&pBhi, g_Bhi);
    cudaGetSymbolAddress((void**)&pBlo, g_Blo);

    cudaFuncSetAttribute((const void*)gemm_mma_kernel<true>,
                         cudaFuncAttributeMaxDynamicSharedMemorySize, SMEM_GEMM);
    cudaFuncSetAttribute((const void*)gemm_mma_kernel<false>,
                         cudaFuncAttributeMaxDynamicSharedMemorySize, SMEM_GEMM);

    const int nA4 = BSM * DD / 4;
    const int nW4 = DD * DD / 4;
    const dim3 ggemm(DD/128, BSM/128);   // (8, 32)

    // Q projection
    split_bf16_kernel<<<nA4/256, 256>>>(q_in, pAhi, pAlo, nA4);
    split_bf16_kernel<<<nW4/256, 256>>>(Wq, pBhi, pBlo, nW4);
    gemm_mma_kernel<true><<<ggemm, 256, SMEM_GEMM>>>(pAhi, pAlo, pBhi, pBlo, bq, pQ);
    // K projection
    split_bf16_kernel<<<nA4/256, 256>>>(k_in, pAhi, pAlo, nA4);
    split_bf16_kernel<<<nW4/256, 256>>>(Wk, pBhi, pBlo, nW4);
    gemm_mma_kernel<true><<<ggemm, 256, SMEM_GEMM>>>(pAhi, pAlo, pBhi, pBlo, bk, pK);
    // V projection
    split_bf16_kernel<<<nA4/256, 256>>>(v_in, pAhi, pAlo, nA4);
    split_bf16_kernel<<<nW4/256, 256>>>(Wv, pBhi, pBlo, nW4);
    gemm_mma_kernel<true><<<ggemm, 256, SMEM_GEMM>>>(pAhi, pAlo, pBhi, pBlo, bv, pV);

    // Attention (linearized) + softmax
    kv_outer_kernel<<<dim3(32, 4), 256>>>();
    mask_scan_kernel<<<dim3(32, 32, 2), 256>>>(mask);
    qt_softmax_kernel<<<dim3(32, 32), 256>>>(mask, pX);

    // Output projection
    split_bf16_kernel<<<nA4/256, 256>>>(pX, pAhi, pAlo, nA4);
    split_bf16_kernel<<<nW4/256, 256>>>(Wo, pBhi, pBlo, nW4);
    gemm_mma_kernel<false><<<ggemm, 256, SMEM_GEMM>>>(pAhi, pAlo, pBhi, pBlo, bo, out);
}

// round 6
// speedup vs baseline: 5.5875x; 1.2042x over previous
#include <cuda_runtime.h>
#include <cuda_bf16.h>
#include <cstddef>
#include <cstdint>

// Problem constants
#define BB 2
#define SS 2048
#define DD 1024
#define HH 16
#define DK 64
#define BSM (BB*SS)
#define NSPLIT 8

typedef unsigned long long u64;

// Scratch (device globals; allocation-free per harness rules).
__device__ float g_Q[(size_t)BB*HH*SS*DK];
__device__ float g_K[(size_t)BB*HH*SS*DK];
__device__ float g_V[(size_t)BB*HH*SS*DK];
__device__ float g_Tp[(size_t)NSPLIT*32*64*64];  // K^T V partials
__device__ float g_T[(size_t)32*64*64];          // reduced, pre-scaled T
__device__ int   g_mflag[2*32*32];
// split-bf16 operands (dedicated per GEMM)
__device__ __nv_bfloat16 g_AQhi[(size_t)BSM*DD];
__device__ __nv_bfloat16 g_AQlo[(size_t)BSM*DD];
__device__ __nv_bfloat16 g_AKhi[(size_t)BSM*DD];
__device__ __nv_bfloat16 g_AKlo[(size_t)BSM*DD];
__device__ __nv_bfloat16 g_AVhi[(size_t)BSM*DD];
__device__ __nv_bfloat16 g_AVlo[(size_t)BSM*DD];
__device__ __nv_bfloat16 g_Xhi[(size_t)BSM*DD];
__device__ __nv_bfloat16 g_Xlo[(size_t)BSM*DD];
__device__ __nv_bfloat16 g_Whi[(size_t)4*DD*DD];
__device__ __nv_bfloat16 g_Wlo[(size_t)4*DD*DD];

// ---------------------------------------------------------------------------
// Packed fp32x2 helpers
// ---------------------------------------------------------------------------
__device__ __forceinline__ u64 pack2(float lo, float hi) {
    u64 r;
    asm("mov.b64 %0, {%1, %2};" : "=l"(r)
        : "r"(__float_as_uint(lo)), "r"(__float_as_uint(hi)));
    return r;
}
__device__ __forceinline__ u64 bcast2(float x) { return pack2(x, x); }
__device__ __forceinline__ void fma2(u64 &d, u64 a, u64 b) {
    asm("fma.rn.f32x2 %0, %1, %2, %0;" : "+l"(d) : "l"(a), "l"(b));
}
__device__ __forceinline__ float2 unpack2(u64 v) {
    unsigned lo, hi;
    asm("mov.b64 {%0, %1}, %2;" : "=r"(lo), "=r"(hi) : "l"(v));
    return make_float2(__uint_as_float(lo), __uint_as_float(hi));
}

// ---------------------------------------------------------------------------
// Warp-MMA helpers (baseline PTX, legal on non-'a' sm_103 target)
// ---------------------------------------------------------------------------
__device__ __forceinline__ uint32_t smem_u32(const void* p) {
    uint32_t a;
    asm("{ .reg .u64 t; cvta.to.shared.u64 t, %1; cvt.u32.u64 %0, t; }"
        : "=r"(a) : "l"(p));
    return a;
}
__device__ __forceinline__ void ldsm_x4(uint32_t* r, uint32_t addr) {
    asm volatile("ldmatrix.sync.aligned.m8n8.x4.shared.b16 {%0,%1,%2,%3}, [%4];"
        : "=r"(r[0]), "=r"(r[1]), "=r"(r[2]), "=r"(r[3]) : "r"(addr));
}
__device__ __forceinline__ void mma_bf16(float* d, const uint32_t* a, const uint32_t* b) {
    asm volatile("mma.sync.aligned.m16n8k16.row.col.f32.bf16.bf16.f32 "
        "{%0,%1,%2,%3}, {%4,%5,%6,%7}, {%8,%9}, {%0,%1,%2,%3};"
        : "+f"(d[0]), "+f"(d[1]), "+f"(d[2]), "+f"(d[3])
        : "r"(a[0]), "r"(a[1]), "r"(a[2]), "r"(a[3]), "r"(b[0]), "r"(b[1]));
}
__device__ __forceinline__ void cp16(uint32_t dst, const void* src) {
    asm volatile("cp.async.cg.shared.global [%0], [%1], 16;" :: "r"(dst), "l"(src));
}
#define CP_COMMIT() asm volatile("cp.async.commit_group;")
#define CP_WAIT(n)  asm volatile("cp.async.wait_group %0;" :: "n"(n))

#define TSTRIDE_B 80
#define TILE_B    (128*TSTRIDE_B)
#define BUF_B     (4*TILE_B)
#define SMEM_GEMM (2*BUF_B)

// ---------------------------------------------------------------------------
// Split helpers
// ---------------------------------------------------------------------------
__device__ __forceinline__ void split_write(__nv_bfloat16* hi, __nv_bfloat16* lo,
                                            int i, float4 v)
{
    __nv_bfloat16 h0 = __float2bfloat16(v.x);
    __nv_bfloat16 h1 = __float2bfloat16(v.y);
    __nv_bfloat16 h2 = __float2bfloat16(v.z);
    __nv_bfloat16 h3 = __float2bfloat16(v.w);
    __nv_bfloat16 l0 = __float2bfloat16(v.x - __bfloat162float(h0));
    __nv_bfloat16 l1 = __float2bfloat16(v.y - __bfloat162float(h1));
    __nv_bfloat16 l2 = __float2bfloat16(v.z - __bfloat162float(h2));
    __nv_bfloat16 l3 = __float2bfloat16(v.w - __bfloat162float(h3));
    ((__nv_bfloat162*)hi)[2*i + 0] = __halves2bfloat162(h0, h1);
    ((__nv_bfloat162*)hi)[2*i + 1] = __halves2bfloat162(h2, h3);
    ((__nv_bfloat162*)lo)[2*i + 0] = __halves2bfloat162(l0, l1);
    ((__nv_bfloat162*)lo)[2*i + 1] = __halves2bfloat162(l2, l3);
}

// Inputs q,k,v -> dedicated bf16 hi/lo buffers. grid.y selects input.
__global__ __launch_bounds__(256)
void split_inputs_kernel(const float* __restrict__ q,
                         const float* __restrict__ k,
                         const float* __restrict__ v)
{
    const int which = blockIdx.y;
    const float* src = (which == 0) ? q : (which == 1) ? k : v;
    __nv_bfloat16* hi = (which == 0) ? g_AQhi : (which == 1) ? g_AKhi : g_AVhi;
    __nv_bfloat16* lo = (which == 0) ? g_AQlo : (which == 1) ? g_AKlo : g_AVlo;
    int i = blockIdx.x * blockDim.x + threadIdx.x;
    split_write(hi, lo, i, ((const float4*)src)[i]);
}

// Weights Wq,Wk,Wv,Wo -> g_Whi/g_Wlo slots 0..3. grid.y selects weight.
__global__ __launch_bounds__(256)
void split_weights_kernel(const float* __restrict__ Wq,
                          const float* __restrict__ Wk,
                          const float* __restrict__ Wv,
                          const float* __restrict__ Wo)
{
    const int which = blockIdx.y;
    const float* src = (which == 0) ? Wq : (which == 1) ? Wk :
                       (which == 2) ? Wv : Wo;
    __nv_bfloat16* hi = g_Whi + (size_t)which * DD * DD;
    __nv_bfloat16* lo = g_Wlo + (size_t)which * DD * DD;
    int i = blockIdx.x * blockDim.x + threadIdx.x;
    split_write(hi, lo, i, ((const float4*)src)[i]);
}

// ---------------------------------------------------------------------------
// mma.sync GEMM-NT, split-bf16 x3 (hh + hl + lh; ll term ~2^-18, dropped).
// Tile 128x128, BK=32, 256 threads (8 warps: 4m x 2n, warp tile 32x64).
// ---------------------------------------------------------------------------
template<bool SPLIT>
__global__ __launch_bounds__(256, 2)
void gemm_mma_kernel(const __nv_bfloat16* __restrict__ Ahi,
                     const __nv_bfloat16* __restrict__ Alo,
                     const __nv_bfloat16* __restrict__ Bhi,
                     const __nv_bfloat16* __restrict__ Blo,
                     const float* __restrict__ Bias,
                     float* __restrict__ Dst)
{
    extern __shared__ char smem[];
    const int tid  = threadIdx.x;
    const int wid  = tid >> 5;
    const int lane = tid & 31;
    const int bm = blockIdx.y * 128;
    const int bn = blockIdx.x * 128;

    const uint32_t sA = smem_u32(smem);

    const char* gT[4] = {
        (const char*)Ahi + (size_t)bm * 2048,
        (const char*)Alo + (size_t)bm * 2048,
        (const char*)Bhi + (size_t)bn * 2048,
        (const char*)Blo + (size_t)bn * 2048
    };

    const int cr = tid >> 2;
    const int cc = (tid & 3) * 16;

    #define STAGE(buf, ck) do {                                              \
        const int kb = (ck) * 64;                                            \
        _Pragma("unroll")                                                    \
        for (int t = 0; t < 4; ++t) {                                        \
            const char* s0 = gT[t] + (size_t)cr * 2048 + kb + cc;            \
            uint32_t d0 = sA + (buf)*BUF_B + t*TILE_B + cr*TSTRIDE_B + cc;   \
            cp16(d0, s0);                                                    \
            cp16(d0 + 64*TSTRIDE_B, s0 + (size_t)64*2048);                   \
        }                                                                    \
    } while (0)

    const int wm = (wid >> 1) * 32;
    const int wn = (wid & 1) * 64;

    const int laA_row = lane & 15;
    const int laA_k   = (lane >> 4) << 3;
    const int laB_row = ((lane >> 4) << 3) + (lane & 7);
    const int laB_k   = ((lane >> 3) & 1) << 3;

    float acc[2][8][4] = {};

    STAGE(0, 0);
    CP_COMMIT();

    for (int ck = 0; ck < 32; ++ck) {
        const int buf = ck & 1;
        if (ck + 1 < 32) {
            STAGE(buf ^ 1, ck + 1);
            CP_COMMIT();
            CP_WAIT(1);
        } else {
            CP_WAIT(0);
        }
        __syncthreads();

        const uint32_t tAh = sA + buf*BUF_B + 0*TILE_B;
        const uint32_t tAl = sA + buf*BUF_B + 1*TILE_B;
        const uint32_t tWh = sA + buf*BUF_B + 2*TILE_B;
        const uint32_t tWl = sA + buf*BUF_B + 3*TILE_B;

        #pragma unroll
        for (int ks = 0; ks < 32; ks += 16) {
            uint32_t a_h[2][4], a_l[2][4];
            #pragma unroll
            for (int mi = 0; mi < 2; ++mi) {
                const uint32_t ao = (uint32_t)((wm + mi*16 + laA_row) * TSTRIDE_B
                                               + (ks + laA_k) * 2);
                ldsm_x4(a_h[mi], tAh + ao);
                ldsm_x4(a_l[mi], tAl + ao);
            }
            #pragma unroll
            for (int j = 0; j < 4; ++j) {
                uint32_t b_h[4], b_l[4];
                const uint32_t bo = (uint32_t)((wn + j*16 + laB_row) * TSTRIDE_B
                                               + (ks + laB_k) * 2);
                ldsm_x4(b_h, tWh + bo);
                ldsm_x4(b_l, tWl + bo);
                #pragma unroll
                for (int mi = 0; mi < 2; ++mi) {
                    #pragma unroll
                    for (int sub = 0; sub < 2; ++sub) {
                        float* d = acc[mi][j*2 + sub];
                        mma_bf16(d, a_h[mi], &b_h[sub*2]);
                        mma_bf16(d, a_h[mi], &b_l[sub*2]);
                        mma_bf16(d, a_l[mi], &b_h[sub*2]);
                    }
                }
            }
        }
        __syncthreads();
    }

    #pragma unroll
    for (int mi = 0; mi < 2; ++mi) {
        #pragma unroll
        for (int nj = 0; nj < 8; ++nj) {
            const int col = bn + wn + nj*8 + (lane & 3)*2;
            const int r0  = bm + wm + mi*16 + (lane >> 2);
            const float b0 = Bias[col], b1 = Bias[col + 1];
            const float* d = acc[mi][nj];
            float2 o0 = { d[0] + b0, d[1] + b1 };
            float2 o1 = { d[2] + b0, d[3] + b1 };
            if (SPLIT) {
                const int h = col >> 6, dk = col & 63;
                const int bA = r0 >> 11, s0 = r0 & (SS - 1);
                float* p0 = Dst + (((size_t)(bA*HH + h) * SS + s0) * DK + dk);
                *(float2*)p0 = o0;
                const int r1 = r0 + 8;
                const int bB = r1 >> 11, s1 = r1 & (SS - 1);
                float* p1 = Dst + (((size_t)(bB*HH + h) * SS + s1) * DK + dk);
                *(float2*)p1 = o1;
            } else {
                *(float2*)(Dst + (size_t)r0 * DD + col)     = o0;
                *(float2*)(Dst + (size_t)(r0+8) * DD + col) = o1;
            }
        }
    }
    #undef STAGE
}

// ---------------------------------------------------------------------------
// Stage A: T_partial[sp][bh] = sum_{s in split} K^T V  (NSPLIT splits)
// ---------------------------------------------------------------------------
__global__ __launch_bounds__(256)
void kv_outer_kernel()
{
    const int bh = blockIdx.x;
    const int sp = blockIdx.y;
    const float* Kh = g_K + (size_t)bh * SS * DK;
    const float* Vh = g_V + (size_t)bh * SS * DK;

    __shared__ float Ks[32][68];
    __shared__ float Vs[32][68];

    const int tid = threadIdx.x;
    const int tx = tid & 15;
    const int ty = tid >> 4;

    u64 acc[4][2] = {};
    const int s0 = sp * (SS / NSPLIT);

    for (int c = 0; c < SS / NSPLIT; c += 32) {
        __syncthreads();
        #pragma unroll
        for (int it = 0; it < 2; ++it) {
            const int lin = tid + it * 256;
            const int r  = lin >> 4;
            const int c4 = (lin & 15) * 4;
            *(float4*)&Ks[r][c4] = *(const float4*)&Kh[(size_t)(s0 + c + r) * DK + c4];
            *(float4*)&Vs[r][c4] = *(const float4*)&Vh[(size_t)(s0 + c + r) * DK + c4];
        }
        __syncthreads();
        #pragma unroll
        for (int s = 0; s < 32; ++s) {
            float4 a = *(const float4*)&Ks[s][ty*4];
            const u64* vp = (const u64*)&Vs[s][tx*4];
            u64 v0 = vp[0], v1 = vp[1];
            fma2(acc[0][0], bcast2(a.x), v0); fma2(acc[0][1], bcast2(a.x), v1);
            fma2(acc[1][0], bcast2(a.y), v0); fma2(acc[1][1], bcast2(a.y), v1);
            fma2(acc[2][0], bcast2(a.z), v0); fma2(acc[2][1], bcast2(a.z), v1);
            fma2(acc[3][0], bcast2(a.w), v0); fma2(acc[3][1], bcast2(a.w), v1);
        }
    }

    float* dst = g_Tp + (size_t)(sp * 32 + bh) * 4096;
    #pragma unroll
    for (int i = 0; i < 4; ++i) {
        float2 p0 = unpack2(acc[i][0]);
        float2 p1 = unpack2(acc[i][1]);
        float4 o = { p0.x, p0.y, p1.x, p1.y };
        *(float4*)&dst[(ty*4 + i) * 64 + tx*4] = o;
    }
}

// Reduce NSPLIT partials -> g_T (pre-scaled by 1/8). Grid 32 blocks.
__global__ __launch_bounds__(256)
void reduce_T_kernel()
{
    const int bh = blockIdx.x;
    const int tid = threadIdx.x;
    #pragma unroll
    for (int it = 0; it < 4; ++it) {
        const int i = tid + it * 256;   // float4 slot 0..1023
        float4 s = {0.f, 0.f, 0.f, 0.f};
        #pragma unroll
        for (int sp = 0; sp < NSPLIT; ++sp) {
            const float4 p = *(const float4*)&g_Tp[(size_t)(sp*32 + bh)*4096 + i*4];
            s.x += p.x; s.y += p.y; s.z += p.z; s.w += p.w;
        }
        float4 o = { s.x*0.125f, s.y*0.125f, s.z*0.125f, s.w*0.125f };
        *(float4*)&g_T[(size_t)bh*4096 + i*4] = o;
    }
}

// ---------------------------------------------------------------------------
// Mask scan: flag each 64x64 mask tile containing any zero.
// ---------------------------------------------------------------------------
__global__ __launch_bounds__(256)
void mask_scan_kernel(const int* __restrict__ mask)
{
    const int kt = blockIdx.x, qt = blockIdx.y, b = blockIdx.z;
    const int* mp = mask + (size_t)b * SS * SS + (size_t)qt * 64 * SS + kt * 64;
    __shared__ int s_bad;
    if (threadIdx.x == 0) s_bad = 0;
    __syncthreads();
    const int r  = threadIdx.x >> 2;
    const int c0 = (threadIdx.x & 3) * 16;
    bool bad = false;
    #pragma unroll
    for (int j = 0; j < 4; ++j) {
        int4 v = *(const int4*)&mp[(size_t)r * SS + c0 + j*4];
        if (v.x == 0 || v.y == 0 || v.z == 0 || v.w == 0) bad = true;
    }
    if (bad) s_bad = 1;
    __syncthreads();
    if (threadIdx.x == 0) g_mflag[(b*32 + qt)*32 + kt] = s_bad;
}

// ---------------------------------------------------------------------------
// Stage B: qkv = Q @ T (+ mask corrections), softmax over DK,
// write X directly as split-bf16 (hi/lo) in [B,S,D] layout.
// ---------------------------------------------------------------------------
__global__ __launch_bounds__(256)
void qt_softmax_kernel(const int* __restrict__ mask)
{
    const int qt = blockIdx.x;
    const int bh = blockIdx.y;
    const int b  = bh >> 4;
    const int h  = bh & (HH - 1);
    const int q0 = qt * 64;

    const float* Qh = g_Q + (size_t)bh * SS * DK;

    __shared__ float Qs[64][68];
    __shared__ float Ts[64][68];
    __shared__ float CK[16][68];
    __shared__ float CV[16][68];
    __shared__ int s_flags[32];
    __shared__ int s_any;

    const int tid = threadIdx.x;

    #pragma unroll
    for (int it = 0; it < 4; ++it) {
        const int lin = tid + it * 256;
        const int d4 = lin >> 6;
        const int q  = lin & 63;
        float4 v = *(const float4*)&Qh[(size_t)(q0 + q) * DK + d4*4];
        Qs[d4*4+0][q] = v.x; Qs[d4*4+1][q] = v.y;
        Qs[d4*4+2][q] = v.z; Qs[d4*4+3][q] = v.w;
    }

    {
        const float* Tb = g_T + (size_t)bh * 4096;
        #pragma unroll
        for (int it = 0; it < 4; ++it) {
            const int lin = tid + it * 256;
            const int d1 = lin >> 4;
            const int c4 = (lin & 15) * 4;
            *(float4*)&Ts[d1][c4] = *(const float4*)(Tb + d1 * 64 + c4);
        }
    }

    if (tid == 0) s_any = 0;
    __syncthreads();
    if (tid < 32) {
        int f = g_mflag[(b*32 + qt)*32 + tid];
        s_flags[tid] = f;
        if (f) s_any = 1;
    }
    __syncthreads();

    const int tx = tid & 15;
    const int ty = tid >> 4;

    u64 acc[4][2] = {};
    #pragma unroll
    for (int d1 = 0; d1 < 64; ++d1) {
        float4 a = *(const float4*)&Qs[d1][ty*4];
        const u64* tp = (const u64*)&Ts[d1][tx*4];
        u64 t0 = tp[0], t1 = tp[1];
        fma2(acc[0][0], bcast2(a.x), t0); fma2(acc[0][1], bcast2(a.x), t1);
        fma2(acc[1][0], bcast2(a.y), t0); fma2(acc[1][1], bcast2(a.y), t1);
        fma2(acc[2][0], bcast2(a.z), t0); fma2(acc[2][1], bcast2(a.z), t1);
        fma2(acc[3][0], bcast2(a.w), t0); fma2(acc[3][1], bcast2(a.w), t1);
    }

    if (s_any) {
        const float* Kh = g_K + (size_t)bh * SS * DK;
        const float* Vh = g_V + (size_t)bh * SS * DK;
        const int* mb = mask + (size_t)b * SS * SS;
        for (int kt = 0; kt < 32; ++kt) {
            if (!s_flags[kt]) continue;
            for (int sub = 0; sub < 4; ++sub) {
                const int kbase = kt*64 + sub*16;
                __syncthreads();
                {
                    const int r  = tid >> 4;
                    const int c4 = (tid & 15) * 4;
                    *(float4*)&CK[r][c4] = *(const float4*)&Kh[(size_t)(kbase + r) * DK + c4];
                    *(float4*)&CV[r][c4] = *(const float4*)&Vh[(size_t)(kbase + r) * DK + c4];
                }
                __syncthreads();
                for (int kk = 0; kk < 16; ++kk) {
                    const u64* vp = (const u64*)&CV[kk][tx*4];
                    u64 v0 = vp[0], v1 = vp[1];
                    #pragma unroll
                    for (int qi = 0; qi < 4; ++qi) {
                        const int q = q0 + ty*4 + qi;
                        if (mb[(size_t)q * SS + kbase + kk] == 0) {
                            float s = 0.f;
                            for (int d1 = 0; d1 < 64; ++d1)
                                s += Qs[d1][ty*4 + qi] * CK[kk][d1];
                            const float coef = -1e9f - s * 0.125f;
                            u64 cz = bcast2(coef);
                            fma2(acc[qi][0], cz, v0);
                            fma2(acc[qi][1], cz, v1);
                        }
                    }
                }
            }
        }
    }

    #pragma unroll
    for (int i = 0; i < 4; ++i) {
        float2 pa = unpack2(acc[i][0]);
        float2 pb = unpack2(acc[i][1]);
        float v0 = pa.x, v1 = pa.y, v2 = pb.x, v3 = pb.y;
        float m = fmaxf(fmaxf(v0, v1), fmaxf(v2, v3));
        #pragma unroll
        for (int off = 8; off >= 1; off >>= 1)
            m = fmaxf(m, __shfl_xor_sync(0xffffffffu, m, off, 16));
        float e0 = __expf(v0 - m);
        float e1 = __expf(v1 - m);
        float e2 = __expf(v2 - m);
        float e3 = __expf(v3 - m);
        float sum = e0 + e1 + e2 + e3;
        #pragma unroll
        for (int off = 8; off >= 1; off >>= 1)
            sum += __shfl_xor_sync(0xffffffffu, sum, off, 16);
        const float inv = 1.0f / sum;
        float4 o = { e0*inv, e1*inv, e2*inv, e3*inv };
        const int s = q0 + ty*4 + i;
        const size_t base = ((size_t)b * SS + s) * DD + h * DK + tx*4;
        // split-bf16 write of X
        __nv_bfloat16 h0 = __float2bfloat16(o.x);
        __nv_bfloat16 h1 = __float2bfloat16(o.y);
        __nv_bfloat16 h2 = __float2bfloat16(o.z);
        __nv_bfloat16 h3 = __float2bfloat16(o.w);
        __nv_bfloat16 l0 = __float2bfloat16(o.x - __bfloat162float(h0));
        __nv_bfloat16 l1 = __float2bfloat16(o.y - __bfloat162float(h1));
        __nv_bfloat16 l2 = __float2bfloat16(o.z - __bfloat162float(h2));
        __nv_bfloat16 l3 = __float2bfloat16(o.w - __bfloat162float(h3));
        *(__nv_bfloat162*)&g_Xhi[base]     = __halves2bfloat162(h0, h1);
        *(__nv_bfloat162*)&g_Xhi[base + 2] = __halves2bfloat162(h2, h3);
        *(__nv_bfloat162*)&g_Xlo[base]     = __halves2bfloat162(l0, l1);
        *(__nv_bfloat162*)&g_Xlo[base + 2] = __halves2bfloat162(l2, l3);
    }
}

// ---------------------------------------------------------------------------
// Launch
// ---------------------------------------------------------------------------
extern "C" void kernel_launch(void* const* d_in, const int* in_sizes, int n_in,
                              void* d_out, int out_size)
{
    (void)in_sizes; (void)n_in; (void)out_size;
    const float* k_in = (const float*)d_in[0];
    const float* q_in = (const float*)d_in[1];
    const float* v_in = (const float*)d_in[2];
    const int*   mask = (const int*)  d_in[3];
    const float* bq = (const float*)d_in[5];
    const float* bk = (const float*)d_in[7];
    const float* bv = (const float*)d_in[9];
    const float* bo = (const float*)d_in[11];
    const float* Wq = (const float*)d_in[4];
    const float* Wk = (const float*)d_in[6];
    const float* Wv = (const float*)d_in[8];
    const float* Wo = (const float*)d_in[10];
    float* out = (float*)d_out;

    float *pQ, *pK, *pV;
    __nv_bfloat16 *pAQh, *pAQl, *pAKh, *pAKl, *pAVh, *pAVl, *pXh, *pXl, *pWh, *pWl;
    cudaGetSymbolAddress((void**)&pQ, g_Q);
    cudaGetSymbolAddress((void**)&pK, g_K);
    cudaGetSymbolAddress((void**)&pV, g_V);
    cudaGetSymbolAddress((void**)&pAQh, g_AQhi);
    cudaGetSymbolAddress((void**)&pAQl, g_AQlo);
    cudaGetSymbolAddress((void**)&pAKh, g_AKhi);
    cudaGetSymbolAddress((void**)&pAKl, g_AKlo);
    cudaGetSymbolAddress((void**)&pAVh, g_AVhi);
    cudaGetSymbolAddress((void**)&pAVl, g_AVlo);
    cudaGetSymbolAddress((void**)&pXh, g_Xhi);
    cudaGetSymbolAddress((void**)&pXl, g_Xlo);
    cudaGetSymbolAddress((void**)&pWh, g_Whi);
    cudaGetSymbolAddress((void**)&pWl, g_Wlo);

    cudaFuncSetAttribute((const void*)gemm_mma_kernel<true>,
                         cudaFuncAttributeMaxDynamicSharedMemorySize, SMEM_GEMM);
    cudaFuncSetAttribute((const void*)gemm_mma_kernel<false>,
                         cudaFuncAttributeMaxDynamicSharedMemorySize, SMEM_GEMM);

    const int nA4 = BSM * DD / 4;
    const int nW4 = DD * DD / 4;
    const dim3 ggemm(DD/128, BSM/128);

    split_inputs_kernel<<<dim3(nA4/256, 3), 256>>>(q_in, k_in, v_in);
    split_weights_kernel<<<dim3(nW4/256, 4), 256>>>(Wq, Wk, Wv, Wo);

    gemm_mma_kernel<true><<<ggemm, 256, SMEM_GEMM>>>(pAQh, pAQl, pWh + 0*(size_t)DD*DD, pWl + 0*(size_t)DD*DD, bq, pQ);
    gemm_mma_kernel<true><<<ggemm, 256, SMEM_GEMM>>>(pAKh, pAKl, pWh + 1*(size_t)DD*DD, pWl + 1*(size_t)DD*DD, bk, pK);
    gemm_mma_kernel<true><<<ggemm, 256, SMEM_GEMM>>>(pAVh, pAVl, pWh + 2*(size_t)DD*DD, pWl + 2*(size_t)DD*DD, bv, pV);

    kv_outer_kernel<<<dim3(32, NSPLIT), 256>>>();
    reduce_T_kernel<<<32, 256>>>();
    mask_scan_kernel<<<dim3(32, 32, 2), 256>>>(mask);
    qt_softmax_kernel<<<dim3(32, 32), 256>>>(mask);

    gemm_mma_kernel<false><<<ggemm, 256, SMEM_GEMM>>>(pXh, pXl, pWh + 3*(size_t)DD*DD, pWl + 3*(size_t)DD*DD, bo, out);
}

// round 7
// speedup vs baseline: 5.7860x; 1.0355x over previous
#include <cuda_runtime.h>
#include <cuda_bf16.h>
#include <cstddef>
#include <cstdint>

// Problem constants
#define BB 2
#define SS 2048
#define DD 1024
#define HH 16
#define DK 64
#define BSM (BB*SS)
#define NSPLIT 8

typedef unsigned long long u64;

// Scratch (device globals; allocation-free per harness rules).
__device__ float g_Q[(size_t)BB*HH*SS*DK];
__device__ float g_K[(size_t)BB*HH*SS*DK];
__device__ float g_V[(size_t)BB*HH*SS*DK];
__device__ float g_Tp[(size_t)NSPLIT*32*64*64];
__device__ float g_T[(size_t)32*64*64];
__device__ int   g_mflag[2*32*32];
__device__ __nv_bfloat16 g_AQhi[(size_t)BSM*DD];
__device__ __nv_bfloat16 g_AQlo[(size_t)BSM*DD];
__device__ __nv_bfloat16 g_AKhi[(size_t)BSM*DD];
__device__ __nv_bfloat16 g_AKlo[(size_t)BSM*DD];
__device__ __nv_bfloat16 g_AVhi[(size_t)BSM*DD];
__device__ __nv_bfloat16 g_AVlo[(size_t)BSM*DD];
__device__ __nv_bfloat16 g_Xhi[(size_t)BSM*DD];
__device__ __nv_bfloat16 g_Xlo[(size_t)BSM*DD];
__device__ __nv_bfloat16 g_Whi[(size_t)4*DD*DD];
__device__ __nv_bfloat16 g_Wlo[(size_t)4*DD*DD];

// ---------------------------------------------------------------------------
// Packed fp32x2 helpers
// ---------------------------------------------------------------------------
__device__ __forceinline__ u64 pack2(float lo, float hi) {
    u64 r;
    asm("mov.b64 %0, {%1, %2};" : "=l"(r)
        : "r"(__float_as_uint(lo)), "r"(__float_as_uint(hi)));
    return r;
}
__device__ __forceinline__ u64 bcast2(float x) { return pack2(x, x); }
__device__ __forceinline__ void fma2(u64 &d, u64 a, u64 b) {
    asm("fma.rn.f32x2 %0, %1, %2, %0;" : "+l"(d) : "l"(a), "l"(b));
}
__device__ __forceinline__ float2 unpack2(u64 v) {
    unsigned lo, hi;
    asm("mov.b64 {%0, %1}, %2;" : "=r"(lo), "=r"(hi) : "l"(v));
    return make_float2(__uint_as_float(lo), __uint_as_float(hi));
}

// ---------------------------------------------------------------------------
// Warp-MMA helpers
// ---------------------------------------------------------------------------
__device__ __forceinline__ uint32_t smem_u32(const void* p) {
    uint32_t a;
    asm("{ .reg .u64 t; cvta.to.shared.u64 t, %1; cvt.u32.u64 %0, t; }"
        : "=r"(a) : "l"(p));
    return a;
}
__device__ __forceinline__ void ldsm_x4(uint32_t* r, uint32_t addr) {
    asm volatile("ldmatrix.sync.aligned.m8n8.x4.shared.b16 {%0,%1,%2,%3}, [%4];"
        : "=r"(r[0]), "=r"(r[1]), "=r"(r[2]), "=r"(r[3]) : "r"(addr));
}
__device__ __forceinline__ void mma_bf16(float* d, const uint32_t* a, const uint32_t* b) {
    asm volatile("mma.sync.aligned.m16n8k16.row.col.f32.bf16.bf16.f32 "
        "{%0,%1,%2,%3}, {%4,%5,%6,%7}, {%8,%9}, {%0,%1,%2,%3};"
        : "+f"(d[0]), "+f"(d[1]), "+f"(d[2]), "+f"(d[3])
        : "r"(a[0]), "r"(a[1]), "r"(a[2]), "r"(a[3]), "r"(b[0]), "r"(b[1]));
}
__device__ __forceinline__ void cp16(uint32_t dst, const void* src) {
    asm volatile("cp.async.cg.shared.global [%0], [%1], 16;" :: "r"(dst), "l"(src));
}
#define CP_COMMIT() asm volatile("cp.async.commit_group;")
#define CP_WAIT(n)  asm volatile("cp.async.wait_group %0;" :: "n"(n))

#define TSTRIDE_B 80
#define TILE_B    (128*TSTRIDE_B)
#define BUF_B     (4*TILE_B)
#define SMEM_GEMM (2*BUF_B)

// ---------------------------------------------------------------------------
// Split helpers
// ---------------------------------------------------------------------------
__device__ __forceinline__ void split_write(__nv_bfloat16* hi, __nv_bfloat16* lo,
                                            int i, float4 v)
{
    __nv_bfloat16 h0 = __float2bfloat16(v.x);
    __nv_bfloat16 h1 = __float2bfloat16(v.y);
    __nv_bfloat16 h2 = __float2bfloat16(v.z);
    __nv_bfloat16 h3 = __float2bfloat16(v.w);
    __nv_bfloat16 l0 = __float2bfloat16(v.x - __bfloat162float(h0));
    __nv_bfloat16 l1 = __float2bfloat16(v.y - __bfloat162float(h1));
    __nv_bfloat16 l2 = __float2bfloat16(v.z - __bfloat162float(h2));
    __nv_bfloat16 l3 = __float2bfloat16(v.w - __bfloat162float(h3));
    ((__nv_bfloat162*)hi)[2*i + 0] = __halves2bfloat162(h0, h1);
    ((__nv_bfloat162*)hi)[2*i + 1] = __halves2bfloat162(h2, h3);
    ((__nv_bfloat162*)lo)[2*i + 0] = __halves2bfloat162(l0, l1);
    ((__nv_bfloat162*)lo)[2*i + 1] = __halves2bfloat162(l2, l3);
}

__global__ __launch_bounds__(256)
void split_inputs_kernel(const float* __restrict__ q,
                         const float* __restrict__ k,
                         const float* __restrict__ v)
{
    const int which = blockIdx.y;
    const float* src = (which == 0) ? q : (which == 1) ? k : v;
    __nv_bfloat16* hi = (which == 0) ? g_AQhi : (which == 1) ? g_AKhi : g_AVhi;
    __nv_bfloat16* lo = (which == 0) ? g_AQlo : (which == 1) ? g_AKlo : g_AVlo;
    int i = blockIdx.x * blockDim.x + threadIdx.x;
    split_write(hi, lo, i, ((const float4*)src)[i]);
}

__global__ __launch_bounds__(256)
void split_weights_kernel(const float* __restrict__ Wq,
                          const float* __restrict__ Wk,
                          const float* __restrict__ Wv,
                          const float* __restrict__ Wo)
{
    const int which = blockIdx.y;
    const float* src = (which == 0) ? Wq : (which == 1) ? Wk :
                       (which == 2) ? Wv : Wo;
    __nv_bfloat16* hi = g_Whi + (size_t)which * DD * DD;
    __nv_bfloat16* lo = g_Wlo + (size_t)which * DD * DD;
    int i = blockIdx.x * blockDim.x + threadIdx.x;
    split_write(hi, lo, i, ((const float4*)src)[i]);
}

// ---------------------------------------------------------------------------
// mma.sync GEMM core: 128 threads (4 warps), CTA tile 128x128, warp tile
// 64x64, BK=32, double-buffered cp.async, split-bf16 x3 (hh+hl+lh).
// ---------------------------------------------------------------------------
template<bool SPLIT>
__device__ __forceinline__
void gemm_body(const char* gAh, const char* gAl,
               const char* gBh, const char* gBl,
               const float* __restrict__ Bias,
               float* __restrict__ Dst,
               int bm, int bn, char* smem)
{
    const int tid  = threadIdx.x;
    const int wid  = tid >> 5;
    const int lane = tid & 31;

    const uint32_t sA = smem_u32(smem);

    const char* gT[4] = { gAh, gAl, gBh, gBl };

    const int cr = tid >> 2;         // 0..31
    const int cc = (tid & 3) * 16;   // 0,16,32,48

    #define STAGE(buf, ck) do {                                                \
        const int kb = (ck) * 64;                                              \
        _Pragma("unroll")                                                      \
        for (int t = 0; t < 4; ++t) {                                          \
            _Pragma("unroll")                                                  \
            for (int g = 0; g < 4; ++g) {                                      \
                const int row = cr + g * 32;                                   \
                const char* s0 = gT[t] + (size_t)row * 2048 + kb + cc;         \
                uint32_t d0 = sA + (buf)*BUF_B + t*TILE_B + row*TSTRIDE_B + cc;\
                cp16(d0, s0);                                                  \
            }                                                                  \
        }                                                                      \
    } while (0)

    const int wm = (wid >> 1) * 64;
    const int wn = (wid & 1) * 64;

    const int laA_row = lane & 15;
    const int laA_k   = (lane >> 4) << 3;
    const int laB_row = ((lane >> 4) << 3) + (lane & 7);
    const int laB_k   = ((lane >> 3) & 1) << 3;

    float acc[4][8][4] = {};

    STAGE(0, 0);
    CP_COMMIT();

    for (int ck = 0; ck < 32; ++ck) {
        const int buf = ck & 1;
        if (ck + 1 < 32) {
            STAGE(buf ^ 1, ck + 1);
            CP_COMMIT();
            CP_WAIT(1);
        } else {
            CP_WAIT(0);
        }
        __syncthreads();

        const uint32_t tAh = sA + buf*BUF_B + 0*TILE_B;
        const uint32_t tAl = sA + buf*BUF_B + 1*TILE_B;
        const uint32_t tWh = sA + buf*BUF_B + 2*TILE_B;
        const uint32_t tWl = sA + buf*BUF_B + 3*TILE_B;

        #pragma unroll
        for (int ks = 0; ks < 32; ks += 16) {
            uint32_t a_h[4][4], a_l[4][4];
            #pragma unroll
            for (int mi = 0; mi < 4; ++mi) {
                const uint32_t ao = (uint32_t)((wm + mi*16 + laA_row) * TSTRIDE_B
                                               + (ks + laA_k) * 2);
                ldsm_x4(a_h[mi], tAh + ao);
                ldsm_x4(a_l[mi], tAl + ao);
            }
            #pragma unroll
            for (int j = 0; j < 4; ++j) {
                uint32_t b_h[4], b_l[4];
                const uint32_t bo = (uint32_t)((wn + j*16 + laB_row) * TSTRIDE_B
                                               + (ks + laB_k) * 2);
                ldsm_x4(b_h, tWh + bo);
                ldsm_x4(b_l, tWl + bo);
                #pragma unroll
                for (int mi = 0; mi < 4; ++mi) {
                    #pragma unroll
                    for (int sub = 0; sub < 2; ++sub) {
                        float* d = acc[mi][j*2 + sub];
                        mma_bf16(d, a_h[mi], &b_h[sub*2]);
                        mma_bf16(d, a_h[mi], &b_l[sub*2]);
                        mma_bf16(d, a_l[mi], &b_h[sub*2]);
                    }
                }
            }
        }
        __syncthreads();
    }

    #pragma unroll
    for (int mi = 0; mi < 4; ++mi) {
        #pragma unroll
        for (int nj = 0; nj < 8; ++nj) {
            const int col = bn + wn + nj*8 + (lane & 3)*2;
            const int r0  = bm + wm + mi*16 + (lane >> 2);
            const float b0 = Bias[col], b1 = Bias[col + 1];
            const float* d = acc[mi][nj];
            float2 o0 = { d[0] + b0, d[1] + b1 };
            float2 o1 = { d[2] + b0, d[3] + b1 };
            if (SPLIT) {
                const int h = col >> 6, dk = col & 63;
                const int bA = r0 >> 11, s0 = r0 & (SS - 1);
                float* p0 = Dst + (((size_t)(bA*HH + h) * SS + s0) * DK + dk);
                *(float2*)p0 = o0;
                const int r1 = r0 + 8;
                const int bB = r1 >> 11, s1 = r1 & (SS - 1);
                float* p1 = Dst + (((size_t)(bB*HH + h) * SS + s1) * DK + dk);
                *(float2*)p1 = o1;
            } else {
                *(float2*)(Dst + (size_t)r0 * DD + col)     = o0;
                *(float2*)(Dst + (size_t)(r0+8) * DD + col) = o1;
            }
        }
    }
    #undef STAGE
}

// Fused QKV projection GEMM: grid.z selects (input, weight slot, bias, dst).
__global__ __launch_bounds__(128, 2)
void gemm_qkv_kernel(const float* __restrict__ bq,
                     const float* __restrict__ bk,
                     const float* __restrict__ bv)
{
    extern __shared__ char smem[];
    const int z  = blockIdx.z;
    const int bm = blockIdx.y * 128;
    const int bn = blockIdx.x * 128;

    const __nv_bfloat16* Ahi = (z == 0) ? g_AQhi : (z == 1) ? g_AKhi : g_AVhi;
    const __nv_bfloat16* Alo = (z == 0) ? g_AQlo : (z == 1) ? g_AKlo : g_AVlo;
    const __nv_bfloat16* Bhi = g_Whi + (size_t)z * DD * DD;
    const __nv_bfloat16* Blo = g_Wlo + (size_t)z * DD * DD;
    const float* Bias = (z == 0) ? bq : (z == 1) ? bk : bv;
    float* Dst = (z == 0) ? g_Q : (z == 1) ? g_K : g_V;

    gemm_body<true>((const char*)Ahi + (size_t)bm * 2048,
                    (const char*)Alo + (size_t)bm * 2048,
                    (const char*)Bhi + (size_t)bn * 2048,
                    (const char*)Blo + (size_t)bn * 2048,
                    Bias, Dst, bm, bn, smem);
}

// Output projection GEMM.
__global__ __launch_bounds__(128, 2)
void gemm_out_kernel(const float* __restrict__ bo, float* __restrict__ out)
{
    extern __shared__ char smem[];
    const int bm = blockIdx.y * 128;
    const int bn = blockIdx.x * 128;
    const __nv_bfloat16* Bhi = g_Whi + (size_t)3 * DD * DD;
    const __nv_bfloat16* Blo = g_Wlo + (size_t)3 * DD * DD;
    gemm_body<false>((const char*)g_Xhi + (size_t)bm * 2048,
                     (const char*)g_Xlo + (size_t)bm * 2048,
                     (const char*)Bhi + (size_t)bn * 2048,
                     (const char*)Blo + (size_t)bn * 2048,
                     bo, out, bm, bn, smem);
}

// ---------------------------------------------------------------------------
// Stage A: T_partial[sp][bh] = sum_{s in split} K^T V
// ---------------------------------------------------------------------------
__global__ __launch_bounds__(256)
void kv_outer_kernel()
{
    const int bh = blockIdx.x;
    const int sp = blockIdx.y;
    const float* Kh = g_K + (size_t)bh * SS * DK;
    const float* Vh = g_V + (size_t)bh * SS * DK;

    __shared__ float Ks[32][68];
    __shared__ float Vs[32][68];

    const int tid = threadIdx.x;
    const int tx = tid & 15;
    const int ty = tid >> 4;

    u64 acc[4][2] = {};
    const int s0 = sp * (SS / NSPLIT);

    for (int c = 0; c < SS / NSPLIT; c += 32) {
        __syncthreads();
        #pragma unroll
        for (int it = 0; it < 2; ++it) {
            const int lin = tid + it * 256;
            const int r  = lin >> 4;
            const int c4 = (lin & 15) * 4;
            *(float4*)&Ks[r][c4] = *(const float4*)&Kh[(size_t)(s0 + c + r) * DK + c4];
            *(float4*)&Vs[r][c4] = *(const float4*)&Vh[(size_t)(s0 + c + r) * DK + c4];
        }
        __syncthreads();
        #pragma unroll
        for (int s = 0; s < 32; ++s) {
            float4 a = *(const float4*)&Ks[s][ty*4];
            const u64* vp = (const u64*)&Vs[s][tx*4];
            u64 v0 = vp[0], v1 = vp[1];
            fma2(acc[0][0], bcast2(a.x), v0); fma2(acc[0][1], bcast2(a.x), v1);
            fma2(acc[1][0], bcast2(a.y), v0); fma2(acc[1][1], bcast2(a.y), v1);
            fma2(acc[2][0], bcast2(a.z), v0); fma2(acc[2][1], bcast2(a.z), v1);
            fma2(acc[3][0], bcast2(a.w), v0); fma2(acc[3][1], bcast2(a.w), v1);
        }
    }

    float* dst = g_Tp + (size_t)(sp * 32 + bh) * 4096;
    #pragma unroll
    for (int i = 0; i < 4; ++i) {
        float2 p0 = unpack2(acc[i][0]);
        float2 p1 = unpack2(acc[i][1]);
        float4 o = { p0.x, p0.y, p1.x, p1.y };
        *(float4*)&dst[(ty*4 + i) * 64 + tx*4] = o;
    }
}

__global__ __launch_bounds__(256)
void reduce_T_kernel()
{
    const int bh = blockIdx.x;
    const int tid = threadIdx.x;
    #pragma unroll
    for (int it = 0; it < 4; ++it) {
        const int i = tid + it * 256;
        float4 s = {0.f, 0.f, 0.f, 0.f};
        #pragma unroll
        for (int sp = 0; sp < NSPLIT; ++sp) {
            const float4 p = *(const float4*)&g_Tp[(size_t)(sp*32 + bh)*4096 + i*4];
            s.x += p.x; s.y += p.y; s.z += p.z; s.w += p.w;
        }
        float4 o = { s.x*0.125f, s.y*0.125f, s.z*0.125f, s.w*0.125f };
        *(float4*)&g_T[(size_t)bh*4096 + i*4] = o;
    }
}

__global__ __launch_bounds__(256)
void mask_scan_kernel(const int* __restrict__ mask)
{
    const int kt = blockIdx.x, qt = blockIdx.y, b = blockIdx.z;
    const int* mp = mask + (size_t)b * SS * SS + (size_t)qt * 64 * SS + kt * 64;
    __shared__ int s_bad;
    if (threadIdx.x == 0) s_bad = 0;
    __syncthreads();
    const int r  = threadIdx.x >> 2;
    const int c0 = (threadIdx.x & 3) * 16;
    bool bad = false;
    #pragma unroll
    for (int j = 0; j < 4; ++j) {
        int4 v = *(const int4*)&mp[(size_t)r * SS + c0 + j*4];
        if (v.x == 0 || v.y == 0 || v.z == 0 || v.w == 0) bad = true;
    }
    if (bad) s_bad = 1;
    __syncthreads();
    if (threadIdx.x == 0) g_mflag[(b*32 + qt)*32 + kt] = s_bad;
}

// ---------------------------------------------------------------------------
// Stage B: qkv = Q @ T (+ mask corrections), softmax over DK,
// write X as split-bf16 in [B,S,D] layout.
// ---------------------------------------------------------------------------
__global__ __launch_bounds__(256)
void qt_softmax_kernel(const int* __restrict__ mask)
{
    const int qt = blockIdx.x;
    const int bh = blockIdx.y;
    const int b  = bh >> 4;
    const int h  = bh & (HH - 1);
    const int q0 = qt * 64;

    const float* Qh = g_Q + (size_t)bh * SS * DK;

    __shared__ float Qs[64][68];
    __shared__ float Ts[64][68];
    __shared__ float CK[16][68];
    __shared__ float CV[16][68];
    __shared__ int s_flags[32];
    __shared__ int s_any;

    const int tid = threadIdx.x;

    #pragma unroll
    for (int it = 0; it < 4; ++it) {
        const int lin = tid + it * 256;
        const int d4 = lin >> 6;
        const int q  = lin & 63;
        float4 v = *(const float4*)&Qh[(size_t)(q0 + q) * DK + d4*4];
        Qs[d4*4+0][q] = v.x; Qs[d4*4+1][q] = v.y;
        Qs[d4*4+2][q] = v.z; Qs[d4*4+3][q] = v.w;
    }

    {
        const float* Tb = g_T + (size_t)bh * 4096;
        #pragma unroll
        for (int it = 0; it < 4; ++it) {
            const int lin = tid + it * 256;
            const int d1 = lin >> 4;
            const int c4 = (lin & 15) * 4;
            *(float4*)&Ts[d1][c4] = *(const float4*)(Tb + d1 * 64 + c4);
        }
    }

    if (tid == 0) s_any = 0;
    __syncthreads();
    if (tid < 32) {
        int f = g_mflag[(b*32 + qt)*32 + tid];
        s_flags[tid] = f;
        if (f) s_any = 1;
    }
    __syncthreads();

    const int tx = tid & 15;
    const int ty = tid >> 4;

    u64 acc[4][2] = {};
    #pragma unroll
    for (int d1 = 0; d1 < 64; ++d1) {
        float4 a = *(const float4*)&Qs[d1][ty*4];
        const u64* tp = (const u64*)&Ts[d1][tx*4];
        u64 t0 = tp[0], t1 = tp[1];
        fma2(acc[0][0], bcast2(a.x), t0); fma2(acc[0][1], bcast2(a.x), t1);
        fma2(acc[1][0], bcast2(a.y), t0); fma2(acc[1][1], bcast2(a.y), t1);
        fma2(acc[2][0], bcast2(a.z), t0); fma2(acc[2][1], bcast2(a.z), t1);
        fma2(acc[3][0], bcast2(a.w), t0); fma2(acc[3][1], bcast2(a.w), t1);
    }

    if (s_any) {
        const float* Kh = g_K + (size_t)bh * SS * DK;
        const float* Vh = g_V + (size_t)bh * SS * DK;
        const int* mb = mask + (size_t)b * SS * SS;
        for (int kt = 0; kt < 32; ++kt) {
            if (!s_flags[kt]) continue;
            for (int sub = 0; sub < 4; ++sub) {
                const int kbase = kt*64 + sub*16;
                __syncthreads();
                {
                    const int r  = tid >> 4;
                    const int c4 = (tid & 15) * 4;
                    *(float4*)&CK[r][c4] = *(const float4*)&Kh[(size_t)(kbase + r) * DK + c4];
                    *(float4*)&CV[r][c4] = *(const float4*)&Vh[(size_t)(kbase + r) * DK + c4];
                }
                __syncthreads();
                for (int kk = 0; kk < 16; ++kk) {
                    const u64* vp = (const u64*)&CV[kk][tx*4];
                    u64 v0 = vp[0], v1 = vp[1];
                    #pragma unroll
                    for (int qi = 0; qi < 4; ++qi) {
                        const int q = q0 + ty*4 + qi;
                        if (mb[(size_t)q * SS + kbase + kk] == 0) {
                            float s = 0.f;
                            for (int d1 = 0; d1 < 64; ++d1)
                                s += Qs[d1][ty*4 + qi] * CK[kk][d1];
                            const float coef = -1e9f - s * 0.125f;
                            u64 cz = bcast2(coef);
                            fma2(acc[qi][0], cz, v0);
                            fma2(acc[qi][1], cz, v1);
                        }
                    }
                }
            }
        }
    }

    #pragma unroll
    for (int i = 0; i < 4; ++i) {
        float2 pa = unpack2(acc[i][0]);
        float2 pb = unpack2(acc[i][1]);
        float v0 = pa.x, v1 = pa.y, v2 = pb.x, v3 = pb.y;
        float m = fmaxf(fmaxf(v0, v1), fmaxf(v2, v3));
        #pragma unroll
        for (int off = 8; off >= 1; off >>= 1)
            m = fmaxf(m, __shfl_xor_sync(0xffffffffu, m, off, 16));
        float e0 = __expf(v0 - m);
        float e1 = __expf(v1 - m);
        float e2 = __expf(v2 - m);
        float e3 = __expf(v3 - m);
        float sum = e0 + e1 + e2 + e3;
        #pragma unroll
        for (int off = 8; off >= 1; off >>= 1)
            sum += __shfl_xor_sync(0xffffffffu, sum, off, 16);
        const float inv = 1.0f / sum;
        float4 o = { e0*inv, e1*inv, e2*inv, e3*inv };
        const int s = q0 + ty*4 + i;
        const size_t base = ((size_t)b * SS + s) * DD + h * DK + tx*4;
        __nv_bfloat16 h0 = __float2bfloat16(o.x);
        __nv_bfloat16 h1 = __float2bfloat16(o.y);
        __nv_bfloat16 h2 = __float2bfloat16(o.z);
        __nv_bfloat16 h3 = __float2bfloat16(o.w);
        __nv_bfloat16 l0 = __float2bfloat16(o.x - __bfloat162float(h0));
        __nv_bfloat16 l1 = __float2bfloat16(o.y - __bfloat162float(h1));
        __nv_bfloat16 l2 = __float2bfloat16(o.z - __bfloat162float(h2));
        __nv_bfloat16 l3 = __float2bfloat16(o.w - __bfloat162float(h3));
        *(__nv_bfloat162*)&g_Xhi[base]     = __halves2bfloat162(h0, h1);
        *(__nv_bfloat162*)&g_Xhi[base + 2] = __halves2bfloat162(h2, h3);
        *(__nv_bfloat162*)&g_Xlo[base]     = __halves2bfloat162(l0, l1);
        *(__nv_bfloat162*)&g_Xlo[base + 2] = __halves2bfloat162(l2, l3);
    }
}

// ---------------------------------------------------------------------------
// Launch
// ---------------------------------------------------------------------------
extern "C" void kernel_launch(void* const* d_in, const int* in_sizes, int n_in,
                              void* d_out, int out_size)
{
    (void)in_sizes; (void)n_in; (void)out_size;
    const float* k_in = (const float*)d_in[0];
    const float* q_in = (const float*)d_in[1];
    const float* v_in = (const float*)d_in[2];
    const int*   mask = (const int*)  d_in[3];
    const float* Wq = (const float*)d_in[4];
    const float* bq = (const float*)d_in[5];
    const float* Wk = (const float*)d_in[6];
    const float* bk = (const float*)d_in[7];
    const float* Wv = (const float*)d_in[8];
    const float* bv = (const float*)d_in[9];
    const float* Wo = (const float*)d_in[10];
    const float* bo = (const float*)d_in[11];
    float* out = (float*)d_out;

    cudaFuncSetAttribute((const void*)gemm_qkv_kernel,
                         cudaFuncAttributeMaxDynamicSharedMemorySize, SMEM_GEMM);
    cudaFuncSetAttribute((const void*)gemm_out_kernel,
                         cudaFuncAttributeMaxDynamicSharedMemorySize, SMEM_GEMM);

    const int nA4 = BSM * DD / 4;
    const int nW4 = DD * DD / 4;

    split_inputs_kernel<<<dim3(nA4/256, 3), 256>>>(q_in, k_in, v_in);
    split_weights_kernel<<<dim3(nW4/256, 4), 256>>>(Wq, Wk, Wv, Wo);

    gemm_qkv_kernel<<<dim3(DD/128, BSM/128, 3), 128, SMEM_GEMM>>>(bq, bk, bv);

    kv_outer_kernel<<<dim3(32, NSPLIT), 256>>>();
    reduce_T_kernel<<<32, 256>>>();
    mask_scan_kernel<<<dim3(32, 32, 2), 256>>>(mask);
    qt_softmax_kernel<<<dim3(32, 32), 256>>>(mask);

    gemm_out_kernel<<<dim3(DD/128, BSM/128), 128, SMEM_GEMM>>>(bo, out);
}

// round 8
// speedup vs baseline: 5.7893x; 1.0006x over previous
#include <cuda_runtime.h>
#include <cuda_bf16.h>
#include <cstddef>
#include <cstdint>

// Problem constants
#define BB 2
#define SS 2048
#define DD 1024
#define HH 16
#define DK 64
#define BSM (BB*SS)
#define NSPLIT 8

typedef unsigned long long u64;

// Scratch (device globals; allocation-free per harness rules).
__device__ float g_Q[(size_t)BB*HH*SS*DK];
__device__ float g_K[(size_t)BB*HH*SS*DK];
__device__ float g_V[(size_t)BB*HH*SS*DK];
__device__ float g_Tp[(size_t)NSPLIT*32*64*64];
__device__ float g_T[(size_t)32*64*64];
__device__ int   g_mflag[2*32*32];
__device__ __nv_bfloat16 g_AQhi[(size_t)BSM*DD];
__device__ __nv_bfloat16 g_AQlo[(size_t)BSM*DD];
__device__ __nv_bfloat16 g_AKhi[(size_t)BSM*DD];
__device__ __nv_bfloat16 g_AKlo[(size_t)BSM*DD];
__device__ __nv_bfloat16 g_AVhi[(size_t)BSM*DD];
__device__ __nv_bfloat16 g_AVlo[(size_t)BSM*DD];
__device__ __nv_bfloat16 g_Xhi[(size_t)BSM*DD];
__device__ __nv_bfloat16 g_Xlo[(size_t)BSM*DD];
__device__ __nv_bfloat16 g_Whi[(size_t)4*DD*DD];
__device__ __nv_bfloat16 g_Wlo[(size_t)4*DD*DD];

// ---------------------------------------------------------------------------
// Packed fp32x2 helpers
// ---------------------------------------------------------------------------
__device__ __forceinline__ u64 pack2(float lo, float hi) {
    u64 r;
    asm("mov.b64 %0, {%1, %2};" : "=l"(r)
        : "r"(__float_as_uint(lo)), "r"(__float_as_uint(hi)));
    return r;
}
__device__ __forceinline__ u64 bcast2(float x) { return pack2(x, x); }
__device__ __forceinline__ void fma2(u64 &d, u64 a, u64 b) {
    asm("fma.rn.f32x2 %0, %1, %2, %0;" : "+l"(d) : "l"(a), "l"(b));
}
__device__ __forceinline__ float2 unpack2(u64 v) {
    unsigned lo, hi;
    asm("mov.b64 {%0, %1}, %2;" : "=r"(lo), "=r"(hi) : "l"(v));
    return make_float2(__uint_as_float(lo), __uint_as_float(hi));
}

// ---------------------------------------------------------------------------
// Warp-MMA helpers
// ---------------------------------------------------------------------------
__device__ __forceinline__ uint32_t smem_u32(const void* p) {
    uint32_t a;
    asm("{ .reg .u64 t; cvta.to.shared.u64 t, %1; cvt.u32.u64 %0, t; }"
        : "=r"(a) : "l"(p));
    return a;
}
__device__ __forceinline__ void ldsm_x4(uint32_t* r, uint32_t addr) {
    asm volatile("ldmatrix.sync.aligned.m8n8.x4.shared.b16 {%0,%1,%2,%3}, [%4];"
        : "=r"(r[0]), "=r"(r[1]), "=r"(r[2]), "=r"(r[3]) : "r"(addr));
}
__device__ __forceinline__ void mma_bf16(float* d, const uint32_t* a, const uint32_t* b) {
    asm volatile("mma.sync.aligned.m16n8k16.row.col.f32.bf16.bf16.f32 "
        "{%0,%1,%2,%3}, {%4,%5,%6,%7}, {%8,%9}, {%0,%1,%2,%3};"
        : "+f"(d[0]), "+f"(d[1]), "+f"(d[2]), "+f"(d[3])
        : "r"(a[0]), "r"(a[1]), "r"(a[2]), "r"(a[3]), "r"(b[0]), "r"(b[1]));
}
__device__ __forceinline__ void cp16(uint32_t dst, const void* src) {
    asm volatile("cp.async.cg.shared.global [%0], [%1], 16;" :: "r"(dst), "l"(src));
}
#define CP_COMMIT() asm volatile("cp.async.commit_group;")
#define CP_WAIT(n)  asm volatile("cp.async.wait_group %0;" :: "n"(n))

#define TSTRIDE_B 80
#define TILE_B    (128*TSTRIDE_B)
#define BUF_B     (4*TILE_B)
#define SMEM_GEMM (2*BUF_B)

// ---------------------------------------------------------------------------
// Split helpers
// ---------------------------------------------------------------------------
__device__ __forceinline__ void split_write(__nv_bfloat16* hi, __nv_bfloat16* lo,
                                            int i, float4 v)
{
    __nv_bfloat16 h0 = __float2bfloat16(v.x);
    __nv_bfloat16 h1 = __float2bfloat16(v.y);
    __nv_bfloat16 h2 = __float2bfloat16(v.z);
    __nv_bfloat16 h3 = __float2bfloat16(v.w);
    __nv_bfloat16 l0 = __float2bfloat16(v.x - __bfloat162float(h0));
    __nv_bfloat16 l1 = __float2bfloat16(v.y - __bfloat162float(h1));
    __nv_bfloat16 l2 = __float2bfloat16(v.z - __bfloat162float(h2));
    __nv_bfloat16 l3 = __float2bfloat16(v.w - __bfloat162float(h3));
    ((__nv_bfloat162*)hi)[2*i + 0] = __halves2bfloat162(h0, h1);
    ((__nv_bfloat162*)hi)[2*i + 1] = __halves2bfloat162(h2, h3);
    ((__nv_bfloat162*)lo)[2*i + 0] = __halves2bfloat162(l0, l1);
    ((__nv_bfloat162*)lo)[2*i + 1] = __halves2bfloat162(l2, l3);
}

__global__ __launch_bounds__(256)
void split_inputs_kernel(const float* __restrict__ q,
                         const float* __restrict__ k,
                         const float* __restrict__ v)
{
    const int which = blockIdx.y;
    const float* src = (which == 0) ? q : (which == 1) ? k : v;
    __nv_bfloat16* hi = (which == 0) ? g_AQhi : (which == 1) ? g_AKhi : g_AVhi;
    __nv_bfloat16* lo = (which == 0) ? g_AQlo : (which == 1) ? g_AKlo : g_AVlo;
    int i = blockIdx.x * blockDim.x + threadIdx.x;
    split_write(hi, lo, i, ((const float4*)src)[i]);
}

__global__ __launch_bounds__(256)
void split_weights_kernel(const float* __restrict__ Wq,
                          const float* __restrict__ Wk,
                          const float* __restrict__ Wv,
                          const float* __restrict__ Wo)
{
    const int which = blockIdx.y;
    const float* src = (which == 0) ? Wq : (which == 1) ? Wk :
                       (which == 2) ? Wv : Wo;
    __nv_bfloat16* hi = g_Whi + (size_t)which * DD * DD;
    __nv_bfloat16* lo = g_Wlo + (size_t)which * DD * DD;
    int i = blockIdx.x * blockDim.x + threadIdx.x;
    split_write(hi, lo, i, ((const float4*)src)[i]);
}

// ---------------------------------------------------------------------------
// mma.sync GEMM core: 128 threads (4 warps), CTA tile 128x128, warp tile
// 64x64, BK=32, double-buffered cp.async, split-bf16 x3 (hh+hl+lh).
// ---------------------------------------------------------------------------
template<bool SPLIT>
__device__ __forceinline__
void gemm_body(const char* gAh, const char* gAl,
               const char* gBh, const char* gBl,
               const float* __restrict__ Bias,
               float* __restrict__ Dst,
               int bm, int bn, char* smem)
{
    const int tid  = threadIdx.x;
    const int wid  = tid >> 5;
    const int lane = tid & 31;

    const uint32_t sA = smem_u32(smem);

    const char* gT[4] = { gAh, gAl, gBh, gBl };

    const int cr = tid >> 2;         // 0..31
    const int cc = (tid & 3) * 16;   // 0,16,32,48

    #define STAGE(buf, ck) do {                                                \
        const int kb = (ck) * 64;                                              \
        _Pragma("unroll")                                                      \
        for (int t = 0; t < 4; ++t) {                                          \
            _Pragma("unroll")                                                  \
            for (int g = 0; g < 4; ++g) {                                      \
                const int row = cr + g * 32;                                   \
                const char* s0 = gT[t] + (size_t)row * 2048 + kb + cc;         \
                uint32_t d0 = sA + (buf)*BUF_B + t*TILE_B + row*TSTRIDE_B + cc;\
                cp16(d0, s0);                                                  \
            }                                                                  \
        }                                                                      \
    } while (0)

    const int wm = (wid >> 1) * 64;
    const int wn = (wid & 1) * 64;

    const int laA_row = lane & 15;
    const int laA_k   = (lane >> 4) << 3;
    const int laB_row = ((lane >> 4) << 3) + (lane & 7);
    const int laB_k   = ((lane >> 3) & 1) << 3;

    float acc[4][8][4] = {};

    STAGE(0, 0);
    CP_COMMIT();

    for (int ck = 0; ck < 32; ++ck) {
        const int buf = ck & 1;
        if (ck + 1 < 32) {
            STAGE(buf ^ 1, ck + 1);
            CP_COMMIT();
            CP_WAIT(1);
        } else {
            CP_WAIT(0);
        }
        __syncthreads();

        const uint32_t tAh = sA + buf*BUF_B + 0*TILE_B;
        const uint32_t tAl = sA + buf*BUF_B + 1*TILE_B;
        const uint32_t tWh = sA + buf*BUF_B + 2*TILE_B;
        const uint32_t tWl = sA + buf*BUF_B + 3*TILE_B;

        #pragma unroll
        for (int ks = 0; ks < 32; ks += 16) {
            uint32_t a_h[4][4], a_l[4][4];
            #pragma unroll
            for (int mi = 0; mi < 4; ++mi) {
                const uint32_t ao = (uint32_t)((wm + mi*16 + laA_row) * TSTRIDE_B
                                               + (ks + laA_k) * 2);
                ldsm_x4(a_h[mi], tAh + ao);
                ldsm_x4(a_l[mi], tAl + ao);
            }
            #pragma unroll
            for (int j = 0; j < 4; ++j) {
                uint32_t b_h[4], b_l[4];
                const uint32_t bo = (uint32_t)((wn + j*16 + laB_row) * TSTRIDE_B
                                               + (ks + laB_k) * 2);
                ldsm_x4(b_h, tWh + bo);
                ldsm_x4(b_l, tWl + bo);
                #pragma unroll
                for (int mi = 0; mi < 4; ++mi) {
                    #pragma unroll
                    for (int sub = 0; sub < 2; ++sub) {
                        float* d = acc[mi][j*2 + sub];
                        mma_bf16(d, a_h[mi], &b_h[sub*2]);
                        mma_bf16(d, a_h[mi], &b_l[sub*2]);
                        mma_bf16(d, a_l[mi], &b_h[sub*2]);
                    }
                }
            }
        }
        __syncthreads();
    }

    #pragma unroll
    for (int mi = 0; mi < 4; ++mi) {
        #pragma unroll
        for (int nj = 0; nj < 8; ++nj) {
            const int col = bn + wn + nj*8 + (lane & 3)*2;
            const int r0  = bm + wm + mi*16 + (lane >> 2);
            const float b0 = Bias[col], b1 = Bias[col + 1];
            const float* d = acc[mi][nj];
            float2 o0 = { d[0] + b0, d[1] + b1 };
            float2 o1 = { d[2] + b0, d[3] + b1 };
            if (SPLIT) {
                const int h = col >> 6, dk = col & 63;
                const int bA = r0 >> 11, s0 = r0 & (SS - 1);
                float* p0 = Dst + (((size_t)(bA*HH + h) * SS + s0) * DK + dk);
                *(float2*)p0 = o0;
                const int r1 = r0 + 8;
                const int bB = r1 >> 11, s1 = r1 & (SS - 1);
                float* p1 = Dst + (((size_t)(bB*HH + h) * SS + s1) * DK + dk);
                *(float2*)p1 = o1;
            } else {
                *(float2*)(Dst + (size_t)r0 * DD + col)     = o0;
                *(float2*)(Dst + (size_t)(r0+8) * DD + col) = o1;
            }
        }
    }
    #undef STAGE
}

// Fused QKV projection GEMM: grid.z selects (input, weight slot, bias, dst).
__global__ __launch_bounds__(128, 2)
void gemm_qkv_kernel(const float* __restrict__ bq,
                     const float* __restrict__ bk,
                     const float* __restrict__ bv)
{
    extern __shared__ char smem[];
    const int z  = blockIdx.z;
    const int bm = blockIdx.y * 128;
    const int bn = blockIdx.x * 128;

    const __nv_bfloat16* Ahi = (z == 0) ? g_AQhi : (z == 1) ? g_AKhi : g_AVhi;
    const __nv_bfloat16* Alo = (z == 0) ? g_AQlo : (z == 1) ? g_AKlo : g_AVlo;
    const __nv_bfloat16* Bhi = g_Whi + (size_t)z * DD * DD;
    const __nv_bfloat16* Blo = g_Wlo + (size_t)z * DD * DD;
    const float* Bias = (z == 0) ? bq : (z == 1) ? bk : bv;
    float* Dst = (z == 0) ? g_Q : (z == 1) ? g_K : g_V;

    gemm_body<true>((const char*)Ahi + (size_t)bm * 2048,
                    (const char*)Alo + (size_t)bm * 2048,
                    (const char*)Bhi + (size_t)bn * 2048,
                    (const char*)Blo + (size_t)bn * 2048,
                    Bias, Dst, bm, bn, smem);
}

// Output projection GEMM.
__global__ __launch_bounds__(128, 2)
void gemm_out_kernel(const float* __restrict__ bo, float* __restrict__ out)
{
    extern __shared__ char smem[];
    const int bm = blockIdx.y * 128;
    const int bn = blockIdx.x * 128;
    const __nv_bfloat16* Bhi = g_Whi + (size_t)3 * DD * DD;
    const __nv_bfloat16* Blo = g_Wlo + (size_t)3 * DD * DD;
    gemm_body<false>((const char*)g_Xhi + (size_t)bm * 2048,
                     (const char*)g_Xlo + (size_t)bm * 2048,
                     (const char*)Bhi + (size_t)bn * 2048,
                     (const char*)Blo + (size_t)bn * 2048,
                     bo, out, bm, bn, smem);
}

// ---------------------------------------------------------------------------
// Stage A: T_partial[sp][bh] = sum_{s in split} K^T V
// ---------------------------------------------------------------------------
__global__ __launch_bounds__(256)
void kv_outer_kernel()
{
    const int bh = blockIdx.x;
    const int sp = blockIdx.y;
    const float* Kh = g_K + (size_t)bh * SS * DK;
    const float* Vh = g_V + (size_t)bh * SS * DK;

    __shared__ float Ks[32][68];
    __shared__ float Vs[32][68];

    const int tid = threadIdx.x;
    const int tx = tid & 15;
    const int ty = tid >> 4;

    u64 acc[4][2] = {};
    const int s0 = sp * (SS / NSPLIT);

    for (int c = 0; c < SS / NSPLIT; c += 32) {
        __syncthreads();
        #pragma unroll
        for (int it = 0; it < 2; ++it) {
            const int lin = tid + it * 256;
            const int r  = lin >> 4;
            const int c4 = (lin & 15) * 4;
            *(float4*)&Ks[r][c4] = *(const float4*)&Kh[(size_t)(s0 + c + r) * DK + c4];
            *(float4*)&Vs[r][c4] = *(const float4*)&Vh[(size_t)(s0 + c + r) * DK + c4];
        }
        __syncthreads();
        #pragma unroll
        for (int s = 0; s < 32; ++s) {
            float4 a = *(const float4*)&Ks[s][ty*4];
            const u64* vp = (const u64*)&Vs[s][tx*4];
            u64 v0 = vp[0], v1 = vp[1];
            fma2(acc[0][0], bcast2(a.x), v0); fma2(acc[0][1], bcast2(a.x), v1);
            fma2(acc[1][0], bcast2(a.y), v0); fma2(acc[1][1], bcast2(a.y), v1);
            fma2(acc[2][0], bcast2(a.z), v0); fma2(acc[2][1], bcast2(a.z), v1);
            fma2(acc[3][0], bcast2(a.w), v0); fma2(acc[3][1], bcast2(a.w), v1);
        }
    }

    float* dst = g_Tp + (size_t)(sp * 32 + bh) * 4096;
    #pragma unroll
    for (int i = 0; i < 4; ++i) {
        float2 p0 = unpack2(acc[i][0]);
        float2 p1 = unpack2(acc[i][1]);
        float4 o = { p0.x, p0.y, p1.x, p1.y };
        *(float4*)&dst[(ty*4 + i) * 64 + tx*4] = o;
    }
}

__global__ __launch_bounds__(256)
void reduce_T_kernel()
{
    const int bh = blockIdx.x;
    const int tid = threadIdx.x;
    #pragma unroll
    for (int it = 0; it < 4; ++it) {
        const int i = tid + it * 256;
        float4 s = {0.f, 0.f, 0.f, 0.f};
        #pragma unroll
        for (int sp = 0; sp < NSPLIT; ++sp) {
            const float4 p = *(const float4*)&g_Tp[(size_t)(sp*32 + bh)*4096 + i*4];
            s.x += p.x; s.y += p.y; s.z += p.z; s.w += p.w;
        }
        float4 o = { s.x*0.125f, s.y*0.125f, s.z*0.125f, s.w*0.125f };
        *(float4*)&g_T[(size_t)bh*4096 + i*4] = o;
    }
}

__global__ __launch_bounds__(256)
void mask_scan_kernel(const int* __restrict__ mask)
{
    const int kt = blockIdx.x, qt = blockIdx.y, b = blockIdx.z;
    const int* mp = mask + (size_t)b * SS * SS + (size_t)qt * 64 * SS + kt * 64;
    __shared__ int s_bad;
    if (threadIdx.x == 0) s_bad = 0;
    __syncthreads();
    const int r  = threadIdx.x >> 2;
    const int c0 = (threadIdx.x & 3) * 16;
    bool bad = false;
    #pragma unroll
    for (int j = 0; j < 4; ++j) {
        int4 v = *(const int4*)&mp[(size_t)r * SS + c0 + j*4];
        if (v.x == 0 || v.y == 0 || v.z == 0 || v.w == 0) bad = true;
    }
    if (bad) s_bad = 1;
    __syncthreads();
    if (threadIdx.x == 0) g_mflag[(b*32 + qt)*32 + kt] = s_bad;
}

// ---------------------------------------------------------------------------
// Stage B: qkv = Q @ T (+ mask corrections), softmax over DK,
// write X as split-bf16 in [B,S,D] layout.
// ---------------------------------------------------------------------------
__global__ __launch_bounds__(256)
void qt_softmax_kernel(const int* __restrict__ mask)
{
    const int qt = blockIdx.x;
    const int bh = blockIdx.y;
    const int b  = bh >> 4;
    const int h  = bh & (HH - 1);
    const int q0 = qt * 64;

    const float* Qh = g_Q + (size_t)bh * SS * DK;

    __shared__ float Qs[64][68];
    __shared__ float Ts[64][68];
    __shared__ float CK[16][68];
    __shared__ float CV[16][68];
    __shared__ int s_flags[32];
    __shared__ int s_any;

    const int tid = threadIdx.x;

    #pragma unroll
    for (int it = 0; it < 4; ++it) {
        const int lin = tid + it * 256;
        const int d4 = lin >> 6;
        const int q  = lin & 63;
        float4 v = *(const float4*)&Qh[(size_t)(q0 + q) * DK + d4*4];
        Qs[d4*4+0][q] = v.x; Qs[d4*4+1][q] = v.y;
        Qs[d4*4+2][q] = v.z; Qs[d4*4+3][q] = v.w;
    }

    {
        const float* Tb = g_T + (size_t)bh * 4096;
        #pragma unroll
        for (int it = 0; it < 4; ++it) {
            const int lin = tid + it * 256;
            const int d1 = lin >> 4;
            const int c4 = (lin & 15) * 4;
            *(float4*)&Ts[d1][c4] = *(const float4*)(Tb + d1 * 64 + c4);
        }
    }

    if (tid == 0) s_any = 0;
    __syncthreads();
    if (tid < 32) {
        int f = g_mflag[(b*32 + qt)*32 + tid];
        s_flags[tid] = f;
        if (f) s_any = 1;
    }
    __syncthreads();

    const int tx = tid & 15;
    const int ty = tid >> 4;

    u64 acc[4][2] = {};
    #pragma unroll
    for (int d1 = 0; d1 < 64; ++d1) {
        float4 a = *(const float4*)&Qs[d1][ty*4];
        const u64* tp = (const u64*)&Ts[d1][tx*4];
        u64 t0 = tp[0], t1 = tp[1];
        fma2(acc[0][0], bcast2(a.x), t0); fma2(acc[0][1], bcast2(a.x), t1);
        fma2(acc[1][0], bcast2(a.y), t0); fma2(acc[1][1], bcast2(a.y), t1);
        fma2(acc[2][0], bcast2(a.z), t0); fma2(acc[2][1], bcast2(a.z), t1);
        fma2(acc[3][0], bcast2(a.w), t0); fma2(acc[3][1], bcast2(a.w), t1);
    }

    if (s_any) {
        const float* Kh = g_K + (size_t)bh * SS * DK;
        const float* Vh = g_V + (size_t)bh * SS * DK;
        const int* mb = mask + (size_t)b * SS * SS;
        for (int kt = 0; kt < 32; ++kt) {
            if (!s_flags[kt]) continue;
            for (int sub = 0; sub < 4; ++sub) {
                const int kbase = kt*64 + sub*16;
                __syncthreads();
                {
                    const int r  = tid >> 4;
                    const int c4 = (tid & 15) * 4;
                    *(float4*)&CK[r][c4] = *(const float4*)&Kh[(size_t)(kbase + r) * DK + c4];
                    *(float4*)&CV[r][c4] = *(const float4*)&Vh[(size_t)(kbase + r) * DK + c4];
                }
                __syncthreads();
                for (int kk = 0; kk < 16; ++kk) {
                    const u64* vp = (const u64*)&CV[kk][tx*4];
                    u64 v0 = vp[0], v1 = vp[1];
                    #pragma unroll
                    for (int qi = 0; qi < 4; ++qi) {
                        const int q = q0 + ty*4 + qi;
                        if (mb[(size_t)q * SS + kbase + kk] == 0) {
                            float s = 0.f;
                            for (int d1 = 0; d1 < 64; ++d1)
                                s += Qs[d1][ty*4 + qi] * CK[kk][d1];
                            const float coef = -1e9f - s * 0.125f;
                            u64 cz = bcast2(coef);
                            fma2(acc[qi][0], cz, v0);
                            fma2(acc[qi][1], cz, v1);
                        }
                    }
                }
            }
        }
    }

    #pragma unroll
    for (int i = 0; i < 4; ++i) {
        float2 pa = unpack2(acc[i][0]);
        float2 pb = unpack2(acc[i][1]);
        float v0 = pa.x, v1 = pa.y, v2 = pb.x, v3 = pb.y;
        float m = fmaxf(fmaxf(v0, v1), fmaxf(v2, v3));
        #pragma unroll
        for (int off = 8; off >= 1; off >>= 1)
            m = fmaxf(m, __shfl_xor_sync(0xffffffffu, m, off, 16));
        float e0 = __expf(v0 - m);
        float e1 = __expf(v1 - m);
        float e2 = __expf(v2 - m);
        float e3 = __expf(v3 - m);
        float sum = e0 + e1 + e2 + e3;
        #pragma unroll
        for (int off = 8; off >= 1; off >>= 1)
            sum += __shfl_xor_sync(0xffffffffu, sum, off, 16);
        const float inv = 1.0f / sum;
        float4 o = { e0*inv, e1*inv, e2*inv, e3*inv };
        const int s = q0 + ty*4 + i;
        const size_t base = ((size_t)b * SS + s) * DD + h * DK + tx*4;
        __nv_bfloat16 h0 = __float2bfloat16(o.x);
        __nv_bfloat16 h1 = __float2bfloat16(o.y);
        __nv_bfloat16 h2 = __float2bfloat16(o.z);
        __nv_bfloat16 h3 = __float2bfloat16(o.w);
        __nv_bfloat16 l0 = __float2bfloat16(o.x - __bfloat162float(h0));
        __nv_bfloat16 l1 = __float2bfloat16(o.y - __bfloat162float(h1));
        __nv_bfloat16 l2 = __float2bfloat16(o.z - __bfloat162float(h2));
        __nv_bfloat16 l3 = __float2bfloat16(o.w - __bfloat162float(h3));
        *(__nv_bfloat162*)&g_Xhi[base]     = __halves2bfloat162(h0, h1);
        *(__nv_bfloat162*)&g_Xhi[base + 2] = __halves2bfloat162(h2, h3);
        *(__nv_bfloat162*)&g_Xlo[base]     = __halves2bfloat162(l0, l1);
        *(__nv_bfloat162*)&g_Xlo[base + 2] = __halves2bfloat162(l2, l3);
    }
}

// ---------------------------------------------------------------------------
// Launch
// ---------------------------------------------------------------------------
extern "C" void kernel_launch(void* const* d_in, const int* in_sizes, int n_in,
                              void* d_out, int out_size)
{
    (void)in_sizes; (void)n_in; (void)out_size;
    const float* k_in = (const float*)d_in[0];
    const float* q_in = (const float*)d_in[1];
    const float* v_in = (const float*)d_in[2];
    const int*   mask = (const int*)  d_in[3];
    const float* Wq = (const float*)d_in[4];
    const float* bq = (const float*)d_in[5];
    const float* Wk = (const float*)d_in[6];
    const float* bk = (const float*)d_in[7];
    const float* Wv = (const float*)d_in[8];
    const float* bv = (const float*)d_in[9];
    const float* Wo = (const float*)d_in[10];
    const float* bo = (const float*)d_in[11];
    float* out = (float*)d_out;

    cudaFuncSetAttribute((const void*)gemm_qkv_kernel,
                         cudaFuncAttributeMaxDynamicSharedMemorySize, SMEM_GEMM);
    cudaFuncSetAttribute((const void*)gemm_out_kernel,
                         cudaFuncAttributeMaxDynamicSharedMemorySize, SMEM_GEMM);

    const int nA4 = BSM * DD / 4;
    const int nW4 = DD * DD / 4;

    split_inputs_kernel<<<dim3(nA4/256, 3), 256>>>(q_in, k_in, v_in);
    split_weights_kernel<<<dim3(nW4/256, 4), 256>>>(Wq, Wk, Wv, Wo);

    gemm_qkv_kernel<<<dim3(DD/128, BSM/128, 3), 128, SMEM_GEMM>>>(bq, bk, bv);

    kv_outer_kernel<<<dim3(32, NSPLIT), 256>>>();
    reduce_T_kernel<<<32, 256>>>();
    mask_scan_kernel<<<dim3(32, 32, 2), 256>>>(mask);
    qt_softmax_kernel<<<dim3(32, 32), 256>>>(mask);

    gemm_out_kernel<<<dim3(DD/128, BSM/128), 128, SMEM_GEMM>>>(bo, out);
}

// round 9
// speedup vs baseline: 6.2772x; 1.0843x over previous
#include <cuda_runtime.h>
#include <cuda_bf16.h>
#include <cstddef>
#include <cstdint>

#define BB 2
#define SS 2048
#define DD 1024
#define HH 16
#define DK 64
#define BSM (BB*SS)
#define NSPLIT 16

typedef unsigned long long u64;

__device__ float g_Q[(size_t)BB*HH*SS*DK];
__device__ float g_K[(size_t)BB*HH*SS*DK];
__device__ float g_V[(size_t)BB*HH*SS*DK];
__device__ float g_X[(size_t)BB*SS*DD];
__device__ float g_Tp[(size_t)NSPLIT*32*64*64];
__device__ float g_T[(size_t)32*64*64];
__device__ int   g_mflag[2*32*32];
__device__ __nv_bfloat16 g_Whi[(size_t)4*DD*DD];
__device__ __nv_bfloat16 g_Wlo[(size_t)4*DD*DD];

// ----- fp32x2 helpers -----
__device__ __forceinline__ u64 pack2(float lo, float hi) {
    u64 r;
    asm("mov.b64 %0, {%1, %2};" : "=l"(r)
        : "r"(__float_as_uint(lo)), "r"(__float_as_uint(hi)));
    return r;
}
__device__ __forceinline__ u64 bcast2(float x) { return pack2(x, x); }
__device__ __forceinline__ void fma2(u64 &d, u64 a, u64 b) {
    asm("fma.rn.f32x2 %0, %1, %2, %0;" : "+l"(d) : "l"(a), "l"(b));
}
__device__ __forceinline__ float2 unpack2(u64 v) {
    unsigned lo, hi;
    asm("mov.b64 {%0, %1}, %2;" : "=r"(lo), "=r"(hi) : "l"(v));
    return make_float2(__uint_as_float(lo), __uint_as_float(hi));
}

// ----- MMA helpers -----
__device__ __forceinline__ uint32_t smem_u32(const void* p) {
    uint32_t a;
    asm("{ .reg .u64 t; cvta.to.shared.u64 t, %1; cvt.u32.u64 %0, t; }"
        : "=r"(a) : "l"(p));
    return a;
}
__device__ __forceinline__ void ldsm_x4(uint32_t* r, uint32_t addr) {
    asm volatile("ldmatrix.sync.aligned.m8n8.x4.shared.b16 {%0,%1,%2,%3}, [%4];"
        : "=r"(r[0]), "=r"(r[1]), "=r"(r[2]), "=r"(r[3]) : "r"(addr));
}
__device__ __forceinline__ void mma_bf16(float* d, const uint32_t* a, const uint32_t* b) {
    asm volatile("mma.sync.aligned.m16n8k16.row.col.f32.bf16.bf16.f32 "
        "{%0,%1,%2,%3}, {%4,%5,%6,%7}, {%8,%9}, {%0,%1,%2,%3};"
        : "+f"(d[0]), "+f"(d[1]), "+f"(d[2]), "+f"(d[3])
        : "r"(a[0]), "r"(a[1]), "r"(a[2]), "r"(a[3]), "r"(b[0]), "r"(b[1]));
}
__device__ __forceinline__ void cp16(uint32_t dst, const void* src) {
    asm volatile("cp.async.cg.shared.global [%0], [%1], 16;" :: "r"(dst), "l"(src));
}
#define CP_COMMIT() asm volatile("cp.async.commit_group;")
#define CP_WAIT(n)  asm volatile("cp.async.wait_group %0;" :: "n"(n))

#define TSTRIDE_B 80
#define TILE_B    (128*TSTRIDE_B)
#define BUF_B     (4*TILE_B)
#define SMEM_GEMM (2*BUF_B)

__device__ __forceinline__ void split4(float4 v, uint2& hi, uint2& lo)
{
    __nv_bfloat16 h0 = __float2bfloat16(v.x), h1 = __float2bfloat16(v.y);
    __nv_bfloat16 h2 = __float2bfloat16(v.z), h3 = __float2bfloat16(v.w);
    __nv_bfloat16 l0 = __float2bfloat16(v.x - __bfloat162float(h0));
    __nv_bfloat16 l1 = __float2bfloat16(v.y - __bfloat162float(h1));
    __nv_bfloat16 l2 = __float2bfloat16(v.z - __bfloat162float(h2));
    __nv_bfloat16 l3 = __float2bfloat16(v.w - __bfloat162float(h3));
    __nv_bfloat162 H0 = __halves2bfloat162(h0, h1), H1 = __halves2bfloat162(h2, h3);
    __nv_bfloat162 L0 = __halves2bfloat162(l0, l1), L1 = __halves2bfloat162(l2, l3);
    hi.x = *(unsigned*)&H0; hi.y = *(unsigned*)&H1;
    lo.x = *(unsigned*)&L0; lo.y = *(unsigned*)&L1;
}

__global__ __launch_bounds__(256)
void split_weights_kernel(const float* __restrict__ Wq, const float* __restrict__ Wk,
                          const float* __restrict__ Wv, const float* __restrict__ Wo)
{
    const int which = blockIdx.y;
    const float* src = (which == 0) ? Wq : (which == 1) ? Wk : (which == 2) ? Wv : Wo;
    __nv_bfloat16* hi = g_Whi + (size_t)which * DD * DD;
    __nv_bfloat16* lo = g_Wlo + (size_t)which * DD * DD;
    int i = blockIdx.x * blockDim.x + threadIdx.x;
    uint2 h, l;
    split4(((const float4*)src)[i], h, l);
    ((uint2*)hi)[i] = h;
    ((uint2*)lo)[i] = l;
}

// ---------------------------------------------------------------------------
// GEMM core: fp32 A (split in-kernel), pre-split bf16 W. 128 threads, 4 warps
// (2x2 of 64x64), CTA 128x128, BK=32, 3-pass split MMA (hh+hl+lh).
// ---------------------------------------------------------------------------
template<bool HEADSPLIT>
__device__ __forceinline__
void gemm_body(const float* __restrict__ gA, const char* gWh, const char* gWl,
               const float* __restrict__ Bias, float* __restrict__ Dst,
               int bm, int bn, char* smem)
{
    const int tid  = threadIdx.x;
    const int wid  = tid >> 5;
    const int lane = tid & 31;
    const uint32_t sA = smem_u32(smem);

    const int arow0 = tid >> 3;          // 0..15, rows +i*16
    const int ac4   = (tid & 7) * 4;     // fp32 col 0..28
    const int wrow0 = tid >> 2;          // 0..31, rows +i*32
    const int wcc   = (tid & 3) * 16;    // byte col

    float4 rA[8];

    #define LOADA(ck) do {                                                    \
        _Pragma("unroll")                                                     \
        for (int i = 0; i < 8; ++i)                                           \
            rA[i] = *(const float4*)(gA + (size_t)(arow0 + i*16) * DD         \
                                        + (ck)*32 + ac4);                     \
    } while (0)
    #define STSA(buf) do {                                                    \
        _Pragma("unroll")                                                     \
        for (int i = 0; i < 8; ++i) {                                         \
            uint2 h, l; split4(rA[i], h, l);                                  \
            char* base = smem + (buf)*BUF_B + (arow0 + i*16)*TSTRIDE_B + ac4*2;\
            *(uint2*)(base) = h; *(uint2*)(base + TILE_B) = l;                \
        }                                                                     \
    } while (0)
    #define STAGEW(buf, ck) do {                                              \
        _Pragma("unroll")                                                     \
        for (int i = 0; i < 4; ++i) {                                         \
            const int row = wrow0 + i*32;                                     \
            const size_t go = (size_t)row * 2048 + (ck)*64 + wcc;             \
            uint32_t d = sA + (buf)*BUF_B + row*TSTRIDE_B + wcc;              \
            cp16(d + 2*TILE_B, gWh + go);                                     \
            cp16(d + 3*TILE_B, gWl + go);                                     \
        }                                                                     \
    } while (0)

    const int wm = (wid >> 1) * 64;
    const int wn = (wid & 1) * 64;
    const int laA_row = lane & 15;
    const int laA_k   = (lane >> 4) << 3;
    const int laB_row = ((lane >> 4) << 3) + (lane & 7);
    const int laB_k   = ((lane >> 3) & 1) << 3;

    float acc[4][8][4] = {};

    LOADA(0);
    STAGEW(0, 0);
    CP_COMMIT();
    STSA(0);

    for (int ck = 0; ck < 32; ++ck) {
        const int buf = ck & 1;
        if (ck + 1 < 32) {
            LOADA(ck + 1);
            STAGEW(buf ^ 1, ck + 1);
            CP_COMMIT();
            CP_WAIT(1);
        } else {
            CP_WAIT(0);
        }
        __syncthreads();

        const uint32_t tAh = sA + buf*BUF_B;
        const uint32_t tAl = tAh + TILE_B;
        const uint32_t tWh = tAh + 2*TILE_B;
        const uint32_t tWl = tAh + 3*TILE_B;

        #pragma unroll
        for (int ks = 0; ks < 32; ks += 16) {
            uint32_t a_h[4][4], a_l[4][4];
            #pragma unroll
            for (int mi = 0; mi < 4; ++mi) {
                const uint32_t ao = (uint32_t)((wm + mi*16 + laA_row) * TSTRIDE_B
                                               + (ks + laA_k) * 2);
                ldsm_x4(a_h[mi], tAh + ao);
                ldsm_x4(a_l[mi], tAl + ao);
            }
            #pragma unroll
            for (int j = 0; j < 4; ++j) {
                uint32_t b_h[4], b_l[4];
                const uint32_t bo = (uint32_t)((wn + j*16 + laB_row) * TSTRIDE_B
                                               + (ks + laB_k) * 2);
                ldsm_x4(b_h, tWh + bo);
                ldsm_x4(b_l, tWl + bo);
                #pragma unroll
                for (int mi = 0; mi < 4; ++mi) {
                    #pragma unroll
                    for (int sub = 0; sub < 2; ++sub) {
                        float* d = acc[mi][j*2 + sub];
                        mma_bf16(d, a_h[mi], &b_h[sub*2]);
                        mma_bf16(d, a_h[mi], &b_l[sub*2]);
                        mma_bf16(d, a_l[mi], &b_h[sub*2]);
                    }
                }
            }
        }
        if (ck + 1 < 32) STSA(buf ^ 1);
        __syncthreads();
    }

    #pragma unroll
    for (int mi = 0; mi < 4; ++mi) {
        #pragma unroll
        for (int nj = 0; nj < 8; ++nj) {
            const int col = bn + wn + nj*8 + (lane & 3)*2;
            const int r0  = bm + wm + mi*16 + (lane >> 2);
            const float b0 = Bias[col], b1 = Bias[col + 1];
            const float* d = acc[mi][nj];
            float2 o0 = { d[0] + b0, d[1] + b1 };
            float2 o1 = { d[2] + b0, d[3] + b1 };
            if (HEADSPLIT) {
                const int h = col >> 6, dk = col & 63;
                const int bA = r0 >> 11, s0 = r0 & (SS - 1);
                *(float2*)(Dst + (((size_t)(bA*HH + h) * SS + s0) * DK + dk)) = o0;
                const int r1 = r0 + 8;
                const int bB = r1 >> 11, s1 = r1 & (SS - 1);
                *(float2*)(Dst + (((size_t)(bB*HH + h) * SS + s1) * DK + dk)) = o1;
            } else {
                *(float2*)(Dst + (size_t)r0 * DD + col)     = o0;
                *(float2*)(Dst + (size_t)(r0+8) * DD + col) = o1;
            }
        }
    }
    #undef LOADA
    #undef STSA
    #undef STAGEW
}

__global__ __launch_bounds__(128)
void gemm_qkv_kernel(const float* __restrict__ q_in, const float* __restrict__ k_in,
                     const float* __restrict__ v_in, const float* __restrict__ bq,
                     const float* __restrict__ bk, const float* __restrict__ bv)
{
    extern __shared__ char smem[];
    const int z  = blockIdx.z;
    const int bm = blockIdx.y * 128;
    const int bn = blockIdx.x * 128;
    const float* A   = (z == 0) ? q_in : (z == 1) ? k_in : v_in;
    const float* Bia = (z == 0) ? bq : (z == 1) ? bk : bv;
    float* Dst       = (z == 0) ? g_Q : (z == 1) ? g_K : g_V;
    gemm_body<true>(A + (size_t)bm * DD,
                    (const char*)(g_Whi + (size_t)z*DD*DD) + (size_t)bn * 2048,
                    (const char*)(g_Wlo + (size_t)z*DD*DD) + (size_t)bn * 2048,
                    Bia, Dst, bm, bn, smem);
}

__global__ __launch_bounds__(128)
void gemm_out_kernel(const float* __restrict__ bo, float* __restrict__ out)
{
    extern __shared__ char smem[];
    const int bm = blockIdx.y * 128;
    const int bn = blockIdx.x * 128;
    gemm_body<false>(g_X + (size_t)bm * DD,
                     (const char*)(g_Whi + (size_t)3*DD*DD) + (size_t)bn * 2048,
                     (const char*)(g_Wlo + (size_t)3*DD*DD) + (size_t)bn * 2048,
                     bo, out, bm, bn, smem);
}

// ----- Stage A: K^T V partials -----
__global__ __launch_bounds__(256)
void kv_outer_kernel()
{
    const int bh = blockIdx.x;
    const int sp = blockIdx.y;
    const float* Kh = g_K + (size_t)bh * SS * DK;
    const float* Vh = g_V + (size_t)bh * SS * DK;

    __shared__ float Ks[32][68];
    __shared__ float Vs[32][68];

    const int tid = threadIdx.x;
    const int tx = tid & 15;
    const int ty = tid >> 4;

    u64 acc[4][2] = {};
    const int s0 = sp * (SS / NSPLIT);

    for (int c = 0; c < SS / NSPLIT; c += 32) {
        __syncthreads();
        #pragma unroll
        for (int it = 0; it < 2; ++it) {
            const int lin = tid + it * 256;
            const int r  = lin >> 4;
            const int c4 = (lin & 15) * 4;
            *(float4*)&Ks[r][c4] = *(const float4*)&Kh[(size_t)(s0 + c + r) * DK + c4];
            *(float4*)&Vs[r][c4] = *(const float4*)&Vh[(size_t)(s0 + c + r) * DK + c4];
        }
        __syncthreads();
        #pragma unroll
        for (int s = 0; s < 32; ++s) {
            float4 a = *(const float4*)&Ks[s][ty*4];
            const u64* vp = (const u64*)&Vs[s][tx*4];
            u64 v0 = vp[0], v1 = vp[1];
            fma2(acc[0][0], bcast2(a.x), v0); fma2(acc[0][1], bcast2(a.x), v1);
            fma2(acc[1][0], bcast2(a.y), v0); fma2(acc[1][1], bcast2(a.y), v1);
            fma2(acc[2][0], bcast2(a.z), v0); fma2(acc[2][1], bcast2(a.z), v1);
            fma2(acc[3][0], bcast2(a.w), v0); fma2(acc[3][1], bcast2(a.w), v1);
        }
    }

    float* dst = g_Tp + (size_t)(sp * 32 + bh) * 4096;
    #pragma unroll
    for (int i = 0; i < 4; ++i) {
        float2 p0 = unpack2(acc[i][0]);
        float2 p1 = unpack2(acc[i][1]);
        float4 o = { p0.x, p0.y, p1.x, p1.y };
        *(float4*)&dst[(ty*4 + i) * 64 + tx*4] = o;
    }
}

__global__ __launch_bounds__(256)
void reduce_T_kernel()
{
    const int bh = blockIdx.x;
    const int tid = threadIdx.x;
    #pragma unroll
    for (int it = 0; it < 4; ++it) {
        const int i = tid + it * 256;
        float4 s = {0.f, 0.f, 0.f, 0.f};
        #pragma unroll
        for (int sp = 0; sp < NSPLIT; ++sp) {
            const float4 p = *(const float4*)&g_Tp[(size_t)(sp*32 + bh)*4096 + i*4];
            s.x += p.x; s.y += p.y; s.z += p.z; s.w += p.w;
        }
        float4 o = { s.x*0.125f, s.y*0.125f, s.z*0.125f, s.w*0.125f };
        *(float4*)&g_T[(size_t)bh*4096 + i*4] = o;
    }
}

__global__ __launch_bounds__(256)
void mask_scan_kernel(const int* __restrict__ mask)
{
    const int kt = blockIdx.x, qt = blockIdx.y, b = blockIdx.z;
    const int* mp = mask + (size_t)b * SS * SS + (size_t)qt * 64 * SS + kt * 64;
    __shared__ int s_bad;
    if (threadIdx.x == 0) s_bad = 0;
    __syncthreads();
    const int r  = threadIdx.x >> 2;
    const int c0 = (threadIdx.x & 3) * 16;
    bool bad = false;
    #pragma unroll
    for (int j = 0; j < 4; ++j) {
        int4 v = *(const int4*)&mp[(size_t)r * SS + c0 + j*4];
        if (v.x == 0 || v.y == 0 || v.z == 0 || v.w == 0) bad = true;
    }
    if (bad) s_bad = 1;
    __syncthreads();
    if (threadIdx.x == 0) g_mflag[(b*32 + qt)*32 + kt] = s_bad;
}

// ----- Stage B: qkv = Q @ T (+ corrections), softmax over DK, write fp32 X -----
__global__ __launch_bounds__(256)
void qt_softmax_kernel(const int* __restrict__ mask)
{
    const int qt = blockIdx.x;
    const int bh = blockIdx.y;
    const int b  = bh >> 4;
    const int h  = bh & (HH - 1);
    const int q0 = qt * 64;

    const float* Qh = g_Q + (size_t)bh * SS * DK;

    __shared__ float Qs[64][68];
    __shared__ float Ts[64][68];
    __shared__ float CK[16][68];
    __shared__ float CV[16][68];
    __shared__ int s_flags[32];
    __shared__ int s_any;

    const int tid = threadIdx.x;

    #pragma unroll
    for (int it = 0; it < 4; ++it) {
        const int lin = tid + it * 256;
        const int d4 = lin >> 6;
        const int q  = lin & 63;
        float4 v = *(const float4*)&Qh[(size_t)(q0 + q) * DK + d4*4];
        Qs[d4*4+0][q] = v.x; Qs[d4*4+1][q] = v.y;
        Qs[d4*4+2][q] = v.z; Qs[d4*4+3][q] = v.w;
    }
    {
        const float* Tb = g_T + (size_t)bh * 4096;
        #pragma unroll
        for (int it = 0; it < 4; ++it) {
            const int lin = tid + it * 256;
            const int d1 = lin >> 4;
            const int c4 = (lin & 15) * 4;
            *(float4*)&Ts[d1][c4] = *(const float4*)(Tb + d1 * 64 + c4);
        }
    }

    if (tid == 0) s_any = 0;
    __syncthreads();
    if (tid < 32) {
        int f = g_mflag[(b*32 + qt)*32 + tid];
        s_flags[tid] = f;
        if (f) s_any = 1;
    }
    __syncthreads();

    const int tx = tid & 15;
    const int ty = tid >> 4;

    u64 acc[4][2] = {};
    #pragma unroll
    for (int d1 = 0; d1 < 64; ++d1) {
        float4 a = *(const float4*)&Qs[d1][ty*4];
        const u64* tp = (const u64*)&Ts[d1][tx*4];
        u64 t0 = tp[0], t1 = tp[1];
        fma2(acc[0][0], bcast2(a.x), t0); fma2(acc[0][1], bcast2(a.x), t1);
        fma2(acc[1][0], bcast2(a.y), t0); fma2(acc[1][1], bcast2(a.y), t1);
        fma2(acc[2][0], bcast2(a.z), t0); fma2(acc[2][1], bcast2(a.z), t1);
        fma2(acc[3][0], bcast2(a.w), t0); fma2(acc[3][1], bcast2(a.w), t1);
    }

    if (s_any) {
        const float* Kh = g_K + (size_t)bh * SS * DK;
        const float* Vh = g_V + (size_t)bh * SS * DK;
        const int* mb = mask + (size_t)b * SS * SS;
        for (int kt = 0; kt < 32; ++kt) {
            if (!s_flags[kt]) continue;
            for (int sub = 0; sub < 4; ++sub) {
                const int kbase = kt*64 + sub*16;
                __syncthreads();
                {
                    const int r  = tid >> 4;
                    const int c4 = (tid & 15) * 4;
                    *(float4*)&CK[r][c4] = *(const float4*)&Kh[(size_t)(kbase + r) * DK + c4];
                    *(float4*)&CV[r][c4] = *(const float4*)&Vh[(size_t)(kbase + r) * DK + c4];
                }
                __syncthreads();
                for (int kk = 0; kk < 16; ++kk) {
                    const u64* vp = (const u64*)&CV[kk][tx*4];
                    u64 v0 = vp[0], v1 = vp[1];
                    #pragma unroll
                    for (int qi = 0; qi < 4; ++qi) {
                        const int q = q0 + ty*4 + qi;
                        if (mb[(size_t)q * SS + kbase + kk] == 0) {
                            float s = 0.f;
                            for (int d1 = 0; d1 < 64; ++d1)
                                s += Qs[d1][ty*4 + qi] * CK[kk][d1];
                            const float coef = -1e9f - s * 0.125f;
                            u64 cz = bcast2(coef);
                            fma2(acc[qi][0], cz, v0);
                            fma2(acc[qi][1], cz, v1);
                        }
                    }
                }
            }
        }
    }

    #pragma unroll
    for (int i = 0; i < 4; ++i) {
        float2 pa = unpack2(acc[i][0]);
        float2 pb = unpack2(acc[i][1]);
        float v0 = pa.x, v1 = pa.y, v2 = pb.x, v3 = pb.y;
        float m = fmaxf(fmaxf(v0, v1), fmaxf(v2, v3));
        #pragma unroll
        for (int off = 8; off >= 1; off >>= 1)
            m = fmaxf(m, __shfl_xor_sync(0xffffffffu, m, off, 16));
        float e0 = __expf(v0 - m);
        float e1 = __expf(v1 - m);
        float e2 = __expf(v2 - m);
        float e3 = __expf(v3 - m);
        float sum = e0 + e1 + e2 + e3;
        #pragma unroll
        for (int off = 8; off >= 1; off >>= 1)
            sum += __shfl_xor_sync(0xffffffffu, sum, off, 16);
        const float inv = 1.0f / sum;
        float4 o = { e0*inv, e1*inv, e2*inv, e3*inv };
        const int s = q0 + ty*4 + i;
        *(float4*)&g_X[((size_t)b * SS + s) * DD + h * DK + tx*4] = o;
    }
}

// ----- Launch -----
extern "C" void kernel_launch(void* const* d_in, const int* in_sizes, int n_in,
                              void* d_out, int out_size)
{
    (void)in_sizes; (void)n_in; (void)out_size;
    const float* k_in = (const float*)d_in[0];
    const float* q_in = (const float*)d_in[1];
    const float* v_in = (const float*)d_in[2];
    const int*   mask = (const int*)  d_in[3];
    const float* Wq = (const float*)d_in[4];
    const float* bq = (const float*)d_in[5];
    const float* Wk = (const float*)d_in[6];
    const float* bk = (const float*)d_in[7];
    const float* Wv = (const float*)d_in[8];
    const float* bv = (const float*)d_in[9];
    const float* Wo = (const float*)d_in[10];
    const float* bo = (const float*)d_in[11];
    float* out = (float*)d_out;

    cudaFuncSetAttribute((const void*)gemm_qkv_kernel,
                         cudaFuncAttributeMaxDynamicSharedMemorySize, SMEM_GEMM);
    cudaFuncSetAttribute((const void*)gemm_out_kernel,
                         cudaFuncAttributeMaxDynamicSharedMemorySize, SMEM_GEMM);

    const int nW4 = DD * DD / 4;

    split_weights_kernel<<<dim3(nW4/256, 4), 256>>>(Wq, Wk, Wv, Wo);
    gemm_qkv_kernel<<<dim3(DD/128, BSM/128, 3), 128, SMEM_GEMM>>>(q_in, k_in, v_in, bq, bk, bv);

    kv_outer_kernel<<<dim3(32, NSPLIT), 256>>>();
    reduce_T_kernel<<<32, 256>>>();
    mask_scan_kernel<<<dim3(32, 32, 2), 256>>>(mask);
    qt_softmax_kernel<<<dim3(32, 32), 256>>>(mask);

    gemm_out_kernel<<<dim3(DD/128, BSM/128), 128, SMEM_GEMM>>>(bo, out);
}